// round 14
// baseline (speedup 1.0000x reference)
#include <cuda_runtime.h>
#include <mma.h>
#include <math.h>
using namespace nvcuda;

// Problem dims
#define Bb 16
#define Ss 64
#define Rr 6
#define Ll 24
#define Dd 128
#define Hh 256
#define BS 1024      // B*S
#define NSEQ 6144    // B*S*R

// smem stage geometry for gemm96_cp_c (floats)
#define ASZ96 (96 * 36)        // 3456
#define BSZ   (192 * 36)       // 6912
#define STAGE (ASZ96 + BSZ)    // 10368
#define SMEMF (2 * STAGE)      // 20736 floats = 82944 B

// gru_step96 small-tile stage geometry (floats)
#define GSTG (96 * 36 + 96 * 36)     // 6912 per stage
#define GSMEMF (2 * GSTG)            // 13824 floats = 55296 B

// intra_attn smem layout (floats)
#define IA_QS 0
#define IA_KS 8448
#define IA_VS 16896
#define IA_PS 25344
#define IA_FLOATS 29504

// ---------------- scratch (device globals; no allocations allowed) ----------------
__device__ float g_Whh_i[768 * 256];
__device__ float g_Wih_i[768 * 128];
__device__ float g_bias_i[2 * 768];
__device__ float g_xw_c[(size_t)Ll * NSEQ * 768];   // time-major, permuted rows
__device__ float g_xw_intra[BS * 768];
__device__ float g_hA[NSEQ * Hh];
__device__ float g_hB[NSEQ * Hh];
__device__ float g_his_last[NSEQ * Hh];
__device__ float g_intra_h[BS * Hh];
__device__ float g_Mrv[NSEQ * 384];
__device__ float g_mpv[BS * 384];
__device__ float g_hp[BS * 288];
__device__ float g_qi[BS * Hh];
__device__ float g_kvi[NSEQ * 512];
__device__ float g_oi[BS * Hh];
__device__ float g_vv[BS * Hh];
__device__ float g_qh[BS * Hh];
__device__ float g_kh[BS * Hh];
__device__ float g_vhp[BS * Hh];
__device__ float g_oh[BS * Hh];
__device__ float g_vh[BS * Hh];
__device__ float g_feat[BS * 640];
__device__ float g_Wq[256 * 384];
__device__ float g_Wkv[512 * 384];
__device__ float g_bias_kv[512];
__device__ float g_Waq[256 * 128];
__device__ float g_Wak[256 * 128];
__device__ float g_Wav[256 * 288];
__device__ float g_Wln[256 * 640];
// length sort
__device__ int g_cnt[Ll];
__device__ int g_perm[NSEQ];

__device__ __forceinline__ float sigmoidf_(float x) {
    return __fdividef(1.f, 1.f + __expf(-x));
}
__device__ __forceinline__ float4 tf32_4(float4 v) {
    v.x = wmma::__float_to_tf32(v.x);
    v.y = wmma::__float_to_tf32(v.y);
    v.z = wmma::__float_to_tf32(v.z);
    v.w = wmma::__float_to_tf32(v.w);
    return v;
}
__device__ __forceinline__ void cp16(float* sdst, const float* gsrc) {
    unsigned saddr = (unsigned)__cvta_generic_to_shared(sdst);
    asm volatile("cp.async.cg.shared.global [%0], [%1], 16;\n" :: "r"(saddr), "l"(gsrc));
}
__device__ __forceinline__ void cp_commit() {
    asm volatile("cp.async.commit_group;\n" ::: "memory");
}

// ---------------- fused length sort (one block) ----------------
__global__ void __launch_bounds__(1024) len_sort_all(const int* __restrict__ lenp) {
    __shared__ int bins_s[32], start_s[32], cur_s[32];
    int tid = threadIdx.x;
    if (tid < 32) { bins_s[tid] = 0; cur_s[tid] = 0; }
    __syncthreads();
    for (int i = tid; i < NSEQ; i += 1024) atomicAdd(&bins_s[lenp[i]], 1);
    __syncthreads();
    if (tid == 0) {
        int s = 0;
        for (int l = Ll; l >= 1; l--) { start_s[l] = s; s += bins_s[l]; }
        for (int t = 0; t < Ll; t++) {
            int c = 0;
            for (int l = t + 1; l <= Ll; l++) c += bins_s[l];
            g_cnt[t] = c;
        }
    }
    __syncthreads();
    for (int i = tid; i < NSEQ; i += 1024) {
        int l = lenp[i];
        int pos = start_s[l] + atomicAdd(&cur_s[l], 1);
        g_perm[pos] = i;
    }
}

// ---------------- weight interleaving ----------------
__global__ void prep_whh_i(const float* __restrict__ w_hh, float* __restrict__ dst) {
    int idx = blockIdx.x * blockDim.x + threadIdx.x;
    if (idx >= 768 * 256) return;
    int row = idx >> 8, k = idx & 255;
    int j = row / 3, g = row % 3;
    dst[idx] = w_hh[(g * 256 + j) * 256 + k];
}
__global__ void prep_wih_i(const float* __restrict__ w_ih, float* __restrict__ dst) {
    int idx = blockIdx.x * blockDim.x + threadIdx.x;
    if (idx >= 768 * 128) return;
    int row = idx >> 7, k = idx & 127;
    int j = row / 3, g = row % 3;
    dst[idx] = w_ih[(g * 256 + j) * 128 + k];
}
__global__ void prep_bias_i(const float* __restrict__ b_ih, const float* __restrict__ b_hh,
                            float* __restrict__ dst) {
    int idx = blockIdx.x * blockDim.x + threadIdx.x;
    if (idx >= 768) return;
    int j = idx / 3, g = idx % 3;
    dst[idx] = b_ih[g * 256 + j];
    dst[768 + idx] = b_hh[g * 256 + j];
}

// ---------------- merged weight padding ----------------
__global__ void pad_all(const float* __restrict__ iq_w, const float* __restrict__ ik_w,
                        const float* __restrict__ iv_w, const float* __restrict__ aq_w,
                        const float* __restrict__ ak_w, const float* __restrict__ av_w,
                        const float* __restrict__ ln_w, const float* __restrict__ ik_b,
                        const float* __restrict__ iv_b) {
    int idx = blockIdx.x * blockDim.x + threadIdx.x;
    if (idx < 98304) { int n = idx / 384, k = idx % 384; g_Wq[idx] = (k < 383) ? iq_w[n * 383 + k] : 0.f; return; }
    idx -= 98304;
    if (idx < 98304) { int n = idx / 384, k = idx % 384; g_Wkv[idx] = (k < 383) ? ik_w[n * 383 + k] : 0.f; return; }
    idx -= 98304;
    if (idx < 98304) { g_Wkv[98304 + idx] = iv_w[idx]; return; }
    idx -= 98304;
    if (idx < 32768) { int n = idx / 128, k = idx % 128; g_Waq[idx] = (k < 127) ? aq_w[n * 127 + k] : 0.f; return; }
    idx -= 32768;
    if (idx < 32768) { int n = idx / 128, k = idx % 128; g_Wak[idx] = (k < 127) ? ak_w[n * 127 + k] : 0.f; return; }
    idx -= 32768;
    if (idx < 73728) { int n = idx / 288, k = idx % 288; g_Wav[idx] = (k < 257) ? av_w[n * 257 + k] : 0.f; return; }
    idx -= 73728;
    if (idx < 163840) { int n = idx / 640, k = idx % 640; g_Wln[idx] = (k < 639) ? ln_w[n * 639 + k] : 0.f; return; }
    idx -= 163840;
    if (idx < 512) g_bias_kv[idx] = (idx < 256) ? ik_b[idx] : iv_b[idx - 256];
}

// ---------------- merged builders ----------------
__global__ void build_all(const float* __restrict__ inter_r, const float* __restrict__ intra_x) {
    int idx = blockIdx.x * blockDim.x + threadIdx.x;
    if (idx < NSEQ * 384) {
        int i = idx / 384, c = idx % 384;
        g_Mrv[idx] = (c < 256) ? g_his_last[i * 256 + c] : inter_r[i * 128 + (c - 256)];
        return;
    }
    idx -= NSEQ * 384;
    if (idx < BS * 384) {
        int i = idx / 384, c = idx % 384;
        float v;
        if (c < 256) v = g_intra_h[i * 256 + c];
        else if (c < 383) v = intra_x[i * 128 + (c - 256)];
        else v = 0.f;
        g_mpv[idx] = v;
        return;
    }
    idx -= BS * 384;
    if (idx < BS * 257) {
        int i = idx / 257, c = idx % 257;
        g_hp[i * 288 + c] = (c < 256) ? g_intra_h[i * 256 + c] : intra_x[i * 128 + 127];
    }
}

// ---------------- compacted xw projection ----------------
// Grid (64, 24): blockIdx.y = t, blockIdx.x = pos-chunk (permuted space).
// Dead chunks (i0 >= cnt[t]) exit immediately: ~48% of the grid does no work.
// A rows gathered via perm; output xw_c[(t*NSEQ + pos)][768] (interleaved gates).
__global__ void __launch_bounds__(256, 2) gemm96_cp_c(
    const float* __restrict__ A,          // inter_his [NSEQ][Ll][128]
    const float* __restrict__ W,          // Wih_i [768][128]
    float* __restrict__ C,                // xw_c
    const int* __restrict__ perm,
    const int* __restrict__ cnt)
{
    extern __shared__ float sm[];
    __shared__ int perm_s[96];
    const int t = blockIdx.y;
    const int i0 = blockIdx.x * 96;
    if (i0 >= cnt[t]) return;

    const int tid = threadIdx.x;
    const int warp = tid >> 5;
    const int wy = warp >> 2, wx = warp & 3;

    if (tid < 96) perm_s[tid] = perm[i0 + tid];
    __syncthreads();

    for (int n0 = 0; n0 < 768; n0 += 192) {
        wmma::fragment<wmma::accumulator, 16, 16, 8, float> acc[3][3];
#pragma unroll
        for (int a = 0; a < 3; a++)
#pragma unroll
            for (int b = 0; b < 3; b++) wmma::fill_fragment(acc[a][b], 0.f);

        auto cp_chunk = [&](int k0, int st) {
            float* As = sm + st * STAGE;
            float* Bs = As + ASZ96;
#pragma unroll
            for (int it = 0; it < 3; it++) {
                int idx = tid + it * 256;
                int r = idx >> 3, k4 = (idx & 7) << 2;
                cp16(As + r * 36 + k4,
                     A + ((size_t)perm_s[r] * Ll + t) * 128 + k0 + k4);
            }
#pragma unroll
            for (int it = 0; it < 6; it++) {
                int idx = tid + it * 256;
                int rr = idx >> 3, k4 = (idx & 7) << 2;
                cp16(Bs + rr * 36 + k4, W + (size_t)(n0 + rr) * 128 + k0 + k4);
            }
            cp_commit();
        };

        cp_chunk(0, 0);
        for (int s = 0; s < 4; s++) {
            if (s + 1 < 4) {
                cp_chunk((s + 1) * 32, (s + 1) & 1);
                asm volatile("cp.async.wait_group 1;\n" ::: "memory");
            } else {
                asm volatile("cp.async.wait_group 0;\n" ::: "memory");
            }
            __syncthreads();
            float* As = sm + (s & 1) * STAGE;
            float* Bs = As + ASZ96;
#pragma unroll
            for (int kk = 0; kk < 32; kk += 8) {
                wmma::fragment<wmma::matrix_a, 16, 16, 8, wmma::precision::tf32, wmma::row_major> af[3];
                wmma::fragment<wmma::matrix_b, 16, 16, 8, wmma::precision::tf32, wmma::col_major> bf[3];
#pragma unroll
                for (int fy = 0; fy < 3; fy++)
                    wmma::load_matrix_sync(af[fy], As + (wy * 48 + fy * 16) * 36 + kk, 36);
#pragma unroll
                for (int fx = 0; fx < 3; fx++)
                    wmma::load_matrix_sync(bf[fx], Bs + (wx * 48 + fx * 16) * 36 + kk, 36);
#pragma unroll
                for (int fy = 0; fy < 3; fy++)
#pragma unroll
                    for (int fx = 0; fx < 3; fx++)
                        wmma::mma_sync(acc[fy][fx], af[fy], bf[fx], acc[fy][fx]);
            }
            __syncthreads();
        }

        float* Cs = sm;
#pragma unroll
        for (int fy = 0; fy < 3; fy++)
#pragma unroll
            for (int fx = 0; fx < 3; fx++)
                wmma::store_matrix_sync(Cs + (wy * 48 + fy * 16) * 196 + wx * 48 + fx * 16,
                                        acc[fy][fx], 196, wmma::mem_row_major);
        __syncthreads();
#pragma unroll
        for (int it = 0; it < 18; it++) {
            int idx = tid + it * 256;
            int row = idx / 48, c4 = (idx % 48) << 2;
            float4 v = *(float4*)(Cs + row * 196 + c4);
            *(float4*)(C + ((size_t)t * NSEQ + i0 + row) * 768 + n0 + c4) = v;
        }
        __syncthreads();
    }
}

// ---------------- fused recurrent GEMM + gate: tile 96x96, 128 thr, 4 blk/SM -------
__global__ void __launch_bounds__(128, 4) gru_step96(
    int t,
    const float* __restrict__ Whh,
    const float* __restrict__ xw,         // time-major permuted xw_c
    const float* __restrict__ bias_i,
    const int* __restrict__ lenp,
    const int* __restrict__ perm,
    const int* __restrict__ cnt,
    const float* __restrict__ h_prev, float* __restrict__ h_out,
    float* __restrict__ his_last)
{
    extern __shared__ float sm[];
    __shared__ int perm_s[96];
    __shared__ int len_s[96];

    const int i0 = blockIdx.x * 96;
    if (i0 >= cnt[t]) return;

    const int n0 = blockIdx.y * 96;
    const int tid = threadIdx.x;
    const int warp = tid >> 5;
    const int wy = warp >> 1, wx = warp & 1;

    if (tid < 96) {
        int p = perm[i0 + tid];
        perm_s[tid] = p;
        len_s[tid] = lenp[p];
    }

    wmma::fragment<wmma::accumulator, 16, 16, 8, float> acc[3][3];
#pragma unroll
    for (int a = 0; a < 3; a++)
#pragma unroll
        for (int b = 0; b < 3; b++) wmma::fill_fragment(acc[a][b], 0.f);

    if (t > 0) {
        auto cp_chunk = [&](int k0, int st) {
            float* As = sm + st * GSTG;
            float* Bs = As + 96 * 36;
#pragma unroll
            for (int it = 0; it < 6; it++) {
                int idx = tid + it * 128;
                int r = idx >> 3, k4 = (idx & 7) << 2;
                cp16(As + r * 36 + k4, h_prev + (size_t)(i0 + r) * 256 + k0 + k4);
            }
#pragma unroll
            for (int it = 0; it < 6; it++) {
                int idx = tid + it * 128;
                int rr = idx >> 3, k4 = (idx & 7) << 2;
                cp16(Bs + rr * 36 + k4, Whh + (size_t)(n0 + rr) * 256 + k0 + k4);
            }
            cp_commit();
        };

        cp_chunk(0, 0);
        for (int s = 0; s < 8; s++) {
            if (s + 1 < 8) {
                cp_chunk((s + 1) * 32, (s + 1) & 1);
                asm volatile("cp.async.wait_group 1;\n" ::: "memory");
            } else {
                asm volatile("cp.async.wait_group 0;\n" ::: "memory");
            }
            __syncthreads();
            float* As = sm + (s & 1) * GSTG;
            float* Bs = As + 96 * 36;
#pragma unroll
            for (int kk = 0; kk < 32; kk += 8) {
                wmma::fragment<wmma::matrix_a, 16, 16, 8, wmma::precision::tf32, wmma::row_major> af[3];
                wmma::fragment<wmma::matrix_b, 16, 16, 8, wmma::precision::tf32, wmma::col_major> bf[3];
#pragma unroll
                for (int fy = 0; fy < 3; fy++)
                    wmma::load_matrix_sync(af[fy], As + (wy * 48 + fy * 16) * 36 + kk, 36);
#pragma unroll
                for (int fx = 0; fx < 3; fx++)
                    wmma::load_matrix_sync(bf[fx], Bs + (wx * 48 + fx * 16) * 36 + kk, 36);
#pragma unroll
                for (int fy = 0; fy < 3; fy++)
#pragma unroll
                    for (int fx = 0; fx < 3; fx++)
                        wmma::mma_sync(acc[fy][fx], af[fy], bf[fx], acc[fy][fx]);
            }
            __syncthreads();
        }
    }

    // ---- single-pass gate epilogue via Cs[96][100]
    float* Cs = sm;
    __syncthreads();
#pragma unroll
    for (int fy = 0; fy < 3; fy++)
#pragma unroll
        for (int fx = 0; fx < 3; fx++)
            wmma::store_matrix_sync(Cs + (wy * 48 + fy * 16) * 100 + wx * 48 + fx * 16,
                                    acc[fy][fx], 100, wmma::mem_row_major);
    __syncthreads();

#pragma unroll
    for (int it = 0; it < 6; it++) {
        int idx = tid + it * 128;
        int row = idx >> 3;
        int q = idx & 7;
        int gi = i0 + row;
        int c = q * 12;
        int j = blockIdx.y * 32 + q * 4;

        float GH[12], XW[12], BI[12], BH[12];
        *(float4*)&GH[0] = *(float4*)(Cs + row * 100 + c);
        *(float4*)&GH[4] = *(float4*)(Cs + row * 100 + c + 4);
        *(float4*)&GH[8] = *(float4*)(Cs + row * 100 + c + 8);
        const float* xwrow = xw + ((size_t)t * NSEQ + gi) * 768 + n0 + c;
        *(float4*)&XW[0] = *(const float4*)(xwrow);
        *(float4*)&XW[4] = *(const float4*)(xwrow + 4);
        *(float4*)&XW[8] = *(const float4*)(xwrow + 8);
        *(float4*)&BI[0] = *(const float4*)(bias_i + n0 + c);
        *(float4*)&BI[4] = *(const float4*)(bias_i + n0 + c + 4);
        *(float4*)&BI[8] = *(const float4*)(bias_i + n0 + c + 8);
        *(float4*)&BH[0] = *(const float4*)(bias_i + 768 + n0 + c);
        *(float4*)&BH[4] = *(const float4*)(bias_i + 768 + n0 + c + 4);
        *(float4*)&BH[8] = *(const float4*)(bias_i + 768 + n0 + c + 8);

        float4 hp = make_float4(0.f, 0.f, 0.f, 0.f);
        if (t > 0) hp = *(const float4*)(h_prev + (size_t)gi * 256 + j);
        float hps[4] = {hp.x, hp.y, hp.z, hp.w};
        float hn[4];
#pragma unroll
        for (int u = 0; u < 4; u++) {
            float r = sigmoidf_(XW[3 * u] + BI[3 * u] + GH[3 * u] + BH[3 * u]);
            float z = sigmoidf_(XW[3 * u + 1] + BI[3 * u + 1] + GH[3 * u + 1] + BH[3 * u + 1]);
            float n = tanhf(XW[3 * u + 2] + BI[3 * u + 2] + r * (GH[3 * u + 2] + BH[3 * u + 2]));
            hn[u] = (1.f - z) * n + z * hps[u];
        }
        float4 hv = make_float4(hn[0], hn[1], hn[2], hn[3]);
        *(float4*)(h_out + (size_t)gi * 256 + j) = hv;
        if (len_s[row] == t + 1)
            *(float4*)(his_last + (size_t)perm_s[row] * 256 + j) = hv;
    }
}

// ---------------- wide tf32 GEMM (intra xw): tile 64x192 ---------------------------
__global__ void __launch_bounds__(256, 2) gemm_tc_wide(
    int M, int K,
    const float* __restrict__ A, int lda,
    const float* __restrict__ W, int ldw,
    float* __restrict__ C, int ldc)
{
    __shared__ float smem[64 * 36 + 192 * 36];
    float* As = smem;
    float* Bs = smem + 64 * 36;
    float* Cs = smem;

    int i0 = blockIdx.x * 64, n0 = blockIdx.y * 192;
    int tid = threadIdx.x;
    int warp = tid >> 5, wy = warp >> 2, wx = warp & 3;

    wmma::fragment<wmma::accumulator, 16, 16, 8, float> acc[2][3];
#pragma unroll
    for (int a = 0; a < 2; a++)
#pragma unroll
        for (int b = 0; b < 3; b++) wmma::fill_fragment(acc[a][b], 0.f);

    float4 ra[2], rb[6];
    auto ldchunk = [&](int k0) {
#pragma unroll
        for (int it = 0; it < 2; it++) {
            int idx = tid + it * 256;
            int r = idx >> 3, k4 = (idx & 7) << 2;
            float4 v = make_float4(0.f, 0.f, 0.f, 0.f);
            if (i0 + r < M) v = *(const float4*)(A + (size_t)(i0 + r) * lda + k0 + k4);
            ra[it] = v;
        }
#pragma unroll
        for (int it = 0; it < 6; it++) {
            int idx = tid + it * 256;
            int c = idx >> 3, k4 = (idx & 7) << 2;
            rb[it] = *(const float4*)(W + (size_t)(n0 + c) * ldw + k0 + k4);
        }
    };
    auto stchunk = [&]() {
#pragma unroll
        for (int it = 0; it < 2; it++) {
            int idx = tid + it * 256;
            int r = idx >> 3, k4 = (idx & 7) << 2;
            *(float4*)(As + r * 36 + k4) = tf32_4(ra[it]);
        }
#pragma unroll
        for (int it = 0; it < 6; it++) {
            int idx = tid + it * 256;
            int c = idx >> 3, k4 = (idx & 7) << 2;
            *(float4*)(Bs + c * 36 + k4) = tf32_4(rb[it]);
        }
    };

    ldchunk(0); stchunk(); __syncthreads();
    for (int k0 = 0; k0 < K; k0 += 32) {
        bool more = (k0 + 32) < K;
        if (more) ldchunk(k0 + 32);
#pragma unroll
        for (int kk = 0; kk < 32; kk += 8) {
            wmma::fragment<wmma::matrix_a, 16, 16, 8, wmma::precision::tf32, wmma::row_major> af[2];
            wmma::fragment<wmma::matrix_b, 16, 16, 8, wmma::precision::tf32, wmma::col_major> bf[3];
#pragma unroll
            for (int fy = 0; fy < 2; fy++)
                wmma::load_matrix_sync(af[fy], As + (wy * 32 + fy * 16) * 36 + kk, 36);
#pragma unroll
            for (int fx = 0; fx < 3; fx++)
                wmma::load_matrix_sync(bf[fx], Bs + (wx * 48 + fx * 16) * 36 + kk, 36);
#pragma unroll
            for (int fy = 0; fy < 2; fy++)
#pragma unroll
                for (int fx = 0; fx < 3; fx++)
                    wmma::mma_sync(acc[fy][fx], af[fy], bf[fx], acc[fy][fx]);
        }
        __syncthreads();
        if (more) { stchunk(); __syncthreads(); }
    }

    for (int pass = 0; pass < 2; pass++) {
        __syncthreads();
        if (wy == pass) {
#pragma unroll
            for (int fy = 0; fy < 2; fy++)
#pragma unroll
                for (int fx = 0; fx < 3; fx++)
                    wmma::store_matrix_sync(Cs + (fy * 16) * 196 + wx * 48 + fx * 16,
                                            acc[fy][fx], 196, wmma::mem_row_major);
        }
        __syncthreads();
#pragma unroll
        for (int it = 0; it < 6; it++) {
            int idx = tid + it * 256;
            int row = idx / 48, c4 = (idx % 48) << 2;
            int gi = i0 + pass * 32 + row;
            if (gi >= M) continue;
            float4 v = *(float4*)(Cs + row * 196 + c4);
            *(float4*)(C + (size_t)gi * ldc + n0 + c4) = v;
        }
    }
}

// ---------------- tf32 GEMM (tile 128x64): C = A @ W^T + bias ----------------------
__global__ void __launch_bounds__(256, 2) gemm_tc(
    int M, int N, int K,
    const float* __restrict__ A, int lda,
    const float* __restrict__ W, int ldw,
    const float* __restrict__ bias,
    float* __restrict__ C, int ldc)
{
    __shared__ float smem[128 * 68];
    float* As = smem;
    float* Bs = smem + 128 * 40;

    int i0 = blockIdx.x * 128, n0 = blockIdx.y * 64;
    int tid = threadIdx.x;
    int warp = tid >> 5;
    int wy = warp >> 1, wx = warp & 1;

    wmma::fragment<wmma::accumulator, 16, 16, 8, float> acc[2][2];
#pragma unroll
    for (int a = 0; a < 2; a++)
#pragma unroll
        for (int b = 0; b < 2; b++) wmma::fill_fragment(acc[a][b], 0.f);

    float4 ra[4], rb[2];
    auto ldchunk = [&](int k0) {
#pragma unroll
        for (int it = 0; it < 4; it++) {
            int idx = tid + it * 256;
            int r = idx >> 3, k4 = (idx & 7) << 2;
            float4 v = make_float4(0.f, 0.f, 0.f, 0.f);
            int gi = i0 + r;
            if (gi < M) v = *(const float4*)(A + (size_t)gi * lda + k0 + k4);
            ra[it] = v;
        }
#pragma unroll
        for (int it = 0; it < 2; it++) {
            int idx = tid + it * 256;
            int n = idx >> 3, k4 = (idx & 7) << 2;
            rb[it] = *(const float4*)(W + (size_t)(n0 + n) * ldw + k0 + k4);
        }
    };
    auto stchunk = [&]() {
#pragma unroll
        for (int it = 0; it < 4; it++) {
            int idx = tid + it * 256;
            int r = idx >> 3, k4 = (idx & 7) << 2;
            *(float4*)(As + r * 40 + k4) = tf32_4(ra[it]);
        }
#pragma unroll
        for (int it = 0; it < 2; it++) {
            int idx = tid + it * 256;
            int n = idx >> 3, k4 = (idx & 7) << 2;
            *(float4*)(Bs + n * 40 + k4) = tf32_4(rb[it]);
        }
    };

    ldchunk(0); stchunk(); __syncthreads();
    for (int k0 = 0; k0 < K; k0 += 32) {
        bool more = (k0 + 32) < K;
        if (more) ldchunk(k0 + 32);
#pragma unroll
        for (int kk = 0; kk < 32; kk += 8) {
            wmma::fragment<wmma::matrix_a, 16, 16, 8, wmma::precision::tf32, wmma::row_major> af[2];
            wmma::fragment<wmma::matrix_b, 16, 16, 8, wmma::precision::tf32, wmma::col_major> bf[2];
#pragma unroll
            for (int fy = 0; fy < 2; fy++)
                wmma::load_matrix_sync(af[fy], As + (wy * 32 + fy * 16) * 40 + kk, 40);
#pragma unroll
            for (int fx = 0; fx < 2; fx++)
                wmma::load_matrix_sync(bf[fx], Bs + (wx * 32 + fx * 16) * 40 + kk, 40);
#pragma unroll
            for (int fy = 0; fy < 2; fy++)
#pragma unroll
                for (int fx = 0; fx < 2; fx++)
                    wmma::mma_sync(acc[fy][fx], af[fy], bf[fx], acc[fy][fx]);
        }
        __syncthreads();
        if (more) { stchunk(); __syncthreads(); }
    }

    float* Cs = smem;
#pragma unroll
    for (int fy = 0; fy < 2; fy++)
#pragma unroll
        for (int fx = 0; fx < 2; fx++)
            wmma::store_matrix_sync(Cs + (wy * 32 + fy * 16) * 68 + wx * 32 + fx * 16,
                                    acc[fy][fx], 68, wmma::mem_row_major);
    __syncthreads();
#pragma unroll
    for (int it = 0; it < 8; it++) {
        int idx = tid + it * 256;
        int r = idx >> 4, c4 = (idx & 15) << 2;
        int gi = i0 + r;
        if (gi >= M) continue;
        float4 v = *(float4*)(Cs + r * 68 + c4);
        if (bias) {
            v.x += bias[n0 + c4];     v.y += bias[n0 + c4 + 1];
            v.z += bias[n0 + c4 + 2]; v.w += bias[n0 + c4 + 3];
        }
        *(float4*)(C + (size_t)gi * ldc + n0 + c4) = v;
    }
}

// ---------------- fused intra GRU (xw interleaved) ----------------
__global__ void __launch_bounds__(768) intra_gru(
    const float* __restrict__ xw_intra,
    const float* __restrict__ w_hh,
    const float* __restrict__ b_ih, const float* __restrict__ b_hh,
    float* __restrict__ intra_h)
{
    int b = blockIdx.x;
    int tid = threadIdx.x;
    __shared__ float h_sh[256];
    __shared__ float gh_sh[768];
    if (tid < 256) h_sh[tid] = 0.f;
    __syncthreads();
    const float4* w4 = (const float4*)(w_hh + (size_t)tid * 256);
    for (int t = 0; t < Ss; t++) {
        float acc = 0.f;
        const float4* h4 = (const float4*)h_sh;
#pragma unroll 16
        for (int k = 0; k < 64; k++) {
            float4 w = w4[k];
            float4 h = h4[k];
            acc += w.x * h.x + w.y * h.y + w.z * h.z + w.w * h.w;
        }
        gh_sh[tid] = acc;
        __syncthreads();
        if (tid < 256) {
            const float* xwrow = xw_intra + ((size_t)b * Ss + t) * 768;
            float r = sigmoidf_(xwrow[3 * tid] + b_ih[tid] + gh_sh[tid] + b_hh[tid]);
            float z = sigmoidf_(xwrow[3 * tid + 1] + b_ih[256 + tid] + gh_sh[256 + tid] + b_hh[256 + tid]);
            float n = tanhf(xwrow[3 * tid + 2] + b_ih[512 + tid] + r * (gh_sh[512 + tid] + b_hh[512 + tid]));
            float hn = (1.f - z) * n + z * h_sh[tid];
            h_sh[tid] = hn;
            intra_h[((size_t)b * Ss + t) * 256 + tid] = hn;
        }
        __syncthreads();
    }
}

// ---------------- build_feat ----------------
__global__ void build_feat(const float* __restrict__ intra_x, const float* __restrict__ wr,
                           const float* __restrict__ vv, const float* __restrict__ vh,
                           const float* __restrict__ intra_h, float* __restrict__ feat) {
    int idx = blockIdx.x * blockDim.x + threadIdx.x;
    if (idx >= BS * 640) return;
    float e0 = expf(wr[0]), e1 = expf(wr[1]);
    float w0 = e0 / (e0 + e1), w1 = 1.f - w0;
    int i = idx / 640, c = idx % 640;
    float v;
    if (c < 256) v = w0 * vv[i * 256 + c] + w1 * vh[i * 256 + c];
    else if (c < 512) v = intra_h[i * 256 + (c - 256)];
    else if (c < 639) v = intra_x[i * 128 + (c - 512)];
    else v = 0.f;
    feat[idx] = v;
}

// ---------------- attention cores ----------------
__global__ void __launch_bounds__(256) inter_attn2(
    const float* __restrict__ qi, const float* __restrict__ kvi, float* __restrict__ oi)
{
    int warp = threadIdx.x >> 5, lane = threadIdx.x & 31;
    int item = blockIdx.x * 8 + warp;
    int row = item >> 1, head = item & 1;
    int off = head * 128 + lane * 4;

    float4 q = *(const float4*)(qi + (size_t)row * 256 + off);
    float p[6];
#pragma unroll
    for (int r = 0; r < 6; r++) {
        float4 k4 = *(const float4*)(kvi + (size_t)(row * 6 + r) * 512 + off);
        float d = q.x * k4.x + q.y * k4.y + q.z * k4.z + q.w * k4.w;
#pragma unroll
        for (int o = 16; o; o >>= 1) d += __shfl_xor_sync(0xffffffffu, d, o);
        p[r] = d * 0.08838834764831843f;
    }
    float mx = p[0];
#pragma unroll
    for (int r = 1; r < 6; r++) mx = fmaxf(mx, p[r]);
    float sum = 0.f;
#pragma unroll
    for (int r = 0; r < 6; r++) { p[r] = expf(p[r] - mx); sum += p[r]; }
    float inv = 1.f / sum;
    float4 acc = make_float4(0.f, 0.f, 0.f, 0.f);
#pragma unroll
    for (int r = 0; r < 6; r++) {
        float4 v4 = *(const float4*)(kvi + (size_t)(row * 6 + r) * 512 + 256 + off);
        float w = p[r] * inv;
        acc.x += w * v4.x; acc.y += w * v4.y; acc.z += w * v4.z; acc.w += w * v4.w;
    }
    *(float4*)(oi + (size_t)row * 256 + off) = acc;
}

__global__ void __launch_bounds__(256) intra_attn2(
    const float* __restrict__ qh, const float* __restrict__ kh,
    const float* __restrict__ vhp, float* __restrict__ oh)
{
    extern __shared__ float sm[];
    float* Qs = sm + IA_QS;
    float* Ks = sm + IA_KS;
    float* Vs = sm + IA_VS;
    float* Ps = sm + IA_PS;

    int head = blockIdx.x, b = blockIdx.y;
    int tid = threadIdx.x;

    for (int idx = tid; idx < 64 * 32; idx += 256) {
        int row = idx >> 5, c4 = (idx & 31) << 2;
        size_t g = (size_t)(b * 64 + row) * 256 + head * 128 + c4;
        *(float4*)(Qs + row * 132 + c4) = *(const float4*)(qh + g);
        *(float4*)(Ks + row * 132 + c4) = *(const float4*)(kh + g);
        *(float4*)(Vs + row * 132 + c4) = *(const float4*)(vhp + g);
    }
    __syncthreads();

    for (int idx = tid; idx < 64 * 64; idx += 256) {
        int tq = idx >> 6, tk = idx & 63;
        if (tk > tq) continue;
        const float4* qp = (const float4*)(Qs + tq * 132);
        const float4* kp = (const float4*)(Ks + tk * 132);
        float acc = 0.f;
#pragma unroll
        for (int k = 0; k < 32; k++) {
            float4 a = qp[k], c = kp[k];
            acc += a.x * c.x + a.y * c.y + a.z * c.z + a.w * c.w;
        }
        Ps[tq * 65 + tk] = acc * 0.08838834764831843f;
    }
    __syncthreads();

    if (tid < 64) {
        int tq = tid;
        float mx = -1e30f;
        for (int k = 0; k <= tq; k++) mx = fmaxf(mx, Ps[tq * 65 + k]);
        float sum = 0.f;
        for (int k = 0; k <= tq; k++) { float e = expf(Ps[tq * 65 + k] - mx); Ps[tq * 65 + k] = e; sum += e; }
        float inv = 1.f / sum;
        for (int k = 0; k <= tq; k++) Ps[tq * 65 + k] *= inv;
    }
    __syncthreads();

    for (int idx = tid; idx < 64 * 32; idx += 256) {
        int tq = idx >> 5, d4 = (idx & 31) << 2;
        float4 acc = make_float4(0.f, 0.f, 0.f, 0.f);
        for (int k = 0; k <= tq; k++) {
            float w = Ps[tq * 65 + k];
            float4 v = *(float4*)(Vs + k * 132 + d4);
            acc.x += w * v.x; acc.y += w * v.y; acc.z += w * v.z; acc.w += w * v.w;
        }
        *(float4*)(oh + (size_t)(b * 64 + tq) * 256 + head * 128 + d4) = acc;
    }
}

// ---------------- launch ----------------
extern "C" void kernel_launch(void* const* d_in, const int* in_sizes, int n_in,
                              void* d_out, int out_size) {
    const float* intra_x   = (const float*)d_in[0];
    const float* inter_his = (const float*)d_in[1];
    const float* inter_r   = (const float*)d_in[2];
    const int*   inter_len = (const int*)d_in[4];
    const float* w_ih = (const float*)d_in[5];
    const float* w_hh = (const float*)d_in[6];
    const float* b_ih = (const float*)d_in[7];
    const float* b_hh = (const float*)d_in[8];
    const float* iq_w = (const float*)d_in[9];
    const float* iq_b = (const float*)d_in[10];
    const float* ik_w = (const float*)d_in[11];
    const float* ik_b = (const float*)d_in[12];
    const float* iv_w = (const float*)d_in[13];
    const float* iv_b = (const float*)d_in[14];
    const float* io_w = (const float*)d_in[15];
    const float* io_b = (const float*)d_in[16];
    const float* aq_w = (const float*)d_in[17];
    const float* aq_b = (const float*)d_in[18];
    const float* ak_w = (const float*)d_in[19];
    const float* ak_b = (const float*)d_in[20];
    const float* av_w = (const float*)d_in[21];
    const float* av_b = (const float*)d_in[22];
    const float* ao_w = (const float*)d_in[23];
    const float* ao_b = (const float*)d_in[24];
    const float* wr   = (const float*)d_in[25];
    const float* ln_w = (const float*)d_in[26];
    const float* ln_b = (const float*)d_in[27];
    float* out = (float*)d_out;

    float *p_Whh_i, *p_Wih_i, *p_bias_i, *p_xw, *p_xw_intra, *p_hA, *p_hB, *p_his, *p_ih;
    float *p_Mrv, *p_mpv, *p_hp, *p_qi, *p_kvi, *p_oi, *p_vv, *p_qh, *p_kh, *p_vhp;
    float *p_oh, *p_vh, *p_feat, *p_Wq, *p_Wkv, *p_bias_kv, *p_Waq, *p_Wak, *p_Wav, *p_Wln;
    int *p_perm, *p_cnt;
    cudaGetSymbolAddress((void**)&p_Whh_i, g_Whh_i);
    cudaGetSymbolAddress((void**)&p_Wih_i, g_Wih_i);
    cudaGetSymbolAddress((void**)&p_bias_i, g_bias_i);
    cudaGetSymbolAddress((void**)&p_xw, g_xw_c);
    cudaGetSymbolAddress((void**)&p_xw_intra, g_xw_intra);
    cudaGetSymbolAddress((void**)&p_hA, g_hA);
    cudaGetSymbolAddress((void**)&p_hB, g_hB);
    cudaGetSymbolAddress((void**)&p_his, g_his_last);
    cudaGetSymbolAddress((void**)&p_ih, g_intra_h);
    cudaGetSymbolAddress((void**)&p_Mrv, g_Mrv);
    cudaGetSymbolAddress((void**)&p_mpv, g_mpv);
    cudaGetSymbolAddress((void**)&p_hp, g_hp);
    cudaGetSymbolAddress((void**)&p_qi, g_qi);
    cudaGetSymbolAddress((void**)&p_kvi, g_kvi);
    cudaGetSymbolAddress((void**)&p_oi, g_oi);
    cudaGetSymbolAddress((void**)&p_vv, g_vv);
    cudaGetSymbolAddress((void**)&p_qh, g_qh);
    cudaGetSymbolAddress((void**)&p_kh, g_kh);
    cudaGetSymbolAddress((void**)&p_vhp, g_vhp);
    cudaGetSymbolAddress((void**)&p_oh, g_oh);
    cudaGetSymbolAddress((void**)&p_vh, g_vh);
    cudaGetSymbolAddress((void**)&p_feat, g_feat);
    cudaGetSymbolAddress((void**)&p_Wq, g_Wq);
    cudaGetSymbolAddress((void**)&p_Wkv, g_Wkv);
    cudaGetSymbolAddress((void**)&p_bias_kv, g_bias_kv);
    cudaGetSymbolAddress((void**)&p_Waq, g_Waq);
    cudaGetSymbolAddress((void**)&p_Wak, g_Wak);
    cudaGetSymbolAddress((void**)&p_Wav, g_Wav);
    cudaGetSymbolAddress((void**)&p_Wln, g_Wln);
    cudaGetSymbolAddress((void**)&p_perm, g_perm);
    cudaGetSymbolAddress((void**)&p_cnt, g_cnt);

    static bool attr_set = false;
    if (!attr_set) {
        cudaFuncSetAttribute(gemm96_cp_c, cudaFuncAttributeMaxDynamicSharedMemorySize, SMEMF * 4);
        cudaFuncSetAttribute(gru_step96, cudaFuncAttributeMaxDynamicSharedMemorySize, GSMEMF * 4);
        cudaFuncSetAttribute(intra_attn2, cudaFuncAttributeMaxDynamicSharedMemorySize, IA_FLOATS * 4);
        attr_set = true;
    }

    // prep
    len_sort_all<<<1, 1024>>>(inter_len);
    prep_whh_i<<<(768 * 256 + 255) / 256, 256>>>(w_hh, p_Whh_i);
    prep_bias_i<<<3, 256>>>(b_ih, b_hh, p_bias_i);
    prep_wih_i<<<(768 * 128 + 255) / 256, 256>>>(w_ih, p_Wih_i);

    // compacted inter input projection: only live (t, pos) chunks compute
    gemm96_cp_c<<<dim3(NSEQ / 96, Ll), 256, SMEMF * 4>>>(inter_his, p_Wih_i, p_xw,
                                                         p_perm, p_cnt);

    // inter GRU chain (len-pruned, permuted space; 96x96 tiles, 4 blocks/SM)
    for (int t = 0; t < Ll; t++) {
        float* h_out  = (t & 1) ? p_hB : p_hA;
        float* h_prev = (t & 1) ? p_hA : p_hB;
        gru_step96<<<dim3(NSEQ / 96, 8), 128, GSMEMF * 4>>>(t, p_Whh_i, p_xw, p_bias_i,
                                                            inter_len, p_perm, p_cnt,
                                                            h_prev, h_out, p_his);
    }

    // intra path
    gemm_tc_wide<<<dim3(16, 4), 256>>>(BS, 128, intra_x, 128, p_Wih_i, 128, p_xw_intra, 768);
    intra_gru<<<Bb, 768>>>(p_xw_intra, w_hh, b_ih, b_hh, p_ih);

    // merged weight padding + builders
    pad_all<<<(598528 + 255) / 256, 256>>>(iq_w, ik_w, iv_w, aq_w, ak_w, av_w, ln_w, ik_b, iv_b);
    build_all<<<(3015680 + 255) / 256, 256>>>(inter_r, intra_x);

    // inter MHA (K/V fused into one N=512 GEMM)
    gemm_tc<<<dim3(8, 4), 256>>>(BS, 256, 384, p_mpv, 384, p_Wq, 384, iq_b, p_qi, 256);
    gemm_tc<<<dim3(48, 8), 256>>>(NSEQ, 512, 384, p_Mrv, 384, p_Wkv, 384, p_bias_kv, p_kvi, 512);
    inter_attn2<<<256, 256>>>(p_qi, p_kvi, p_oi);
    gemm_tc<<<dim3(8, 4), 256>>>(BS, 256, 256, p_oi, 256, io_w, 256, io_b, p_vv, 256);

    // intra MHA
    gemm_tc<<<dim3(8, 4), 256>>>(BS, 256, 128, intra_x, 128, p_Waq, 128, aq_b, p_qh, 256);
    gemm_tc<<<dim3(8, 4), 256>>>(BS, 256, 128, intra_x, 128, p_Wak, 128, ak_b, p_kh, 256);
    gemm_tc<<<dim3(8, 4), 256>>>(BS, 256, 288, p_hp, 288, p_Wav, 288, av_b, p_vhp, 256);
    intra_attn2<<<dim3(2, 16), 256, IA_FLOATS * 4>>>(p_qh, p_kh, p_vhp, p_oh);
    gemm_tc<<<dim3(8, 4), 256>>>(BS, 256, 256, p_oh, 256, ao_w, 256, ao_b, p_vh, 256);

    // combine + final projection
    build_feat<<<(BS * 640 + 255) / 256, 256>>>(intra_x, wr, p_vv, p_vh, p_ih, p_feat);
    gemm_tc<<<dim3(8, 4), 256>>>(BS, 256, 640, p_feat, 640, p_Wln, 640, ln_b, out, 256);
}

// round 15
// speedup vs baseline: 1.8333x; 1.8333x over previous
#include <cuda_runtime.h>
#include <mma.h>
#include <math.h>
using namespace nvcuda;

// Problem dims
#define Bb 16
#define Ss 64
#define Rr 6
#define Ll 24
#define Dd 128
#define Hh 256
#define BS 1024      // B*S
#define NSEQ 6144    // B*S*R
#define NROWS_XW (NSEQ * Ll)   // 147456

// smem stage geometry for gemm96_cp (floats)
#define ASZ96 (96 * 36)        // 3456
#define BSZ   (192 * 36)       // 6912
#define STAGE (ASZ96 + BSZ)    // 10368
#define SMEMF (2 * STAGE)      // 20736 floats = 82944 B

// gru_step96 small-tile stage geometry (floats)
#define GSTG (96 * 36 + 96 * 36)     // 6912 per stage
#define GSMEMF (2 * GSTG)            // 13824 floats = 55296 B

// intra_attn smem layout (floats)
#define IA_QS 0
#define IA_KS 8448
#define IA_VS 16896
#define IA_PS 25344
#define IA_FLOATS 29504

// ---------------- scratch (device globals; no allocations allowed) ----------------
__device__ float g_Whh_i[768 * 256];
__device__ float g_WhhT[256 * 768];     // transposed: [k][row] for coalesced intra_gru
__device__ float g_Wih_i[768 * 128];
__device__ float g_bias_i[2 * 768];
__device__ float g_xw_inter[(size_t)NROWS_XW * 768];
__device__ float g_xw_intra[BS * 768];
__device__ float g_hA[NSEQ * Hh];
__device__ float g_hB[NSEQ * Hh];
__device__ float g_his_last[NSEQ * Hh];
__device__ float g_intra_h[BS * Hh];
__device__ float g_Mrv[NSEQ * 384];
__device__ float g_mpv[BS * 384];
__device__ float g_hp[BS * 288];
__device__ float g_qi[BS * Hh];
__device__ float g_kvi[NSEQ * 512];
__device__ float g_oi[BS * Hh];
__device__ float g_vv[BS * Hh];
__device__ float g_qkh[BS * 512];       // fused intra q|k projections
__device__ float g_vhp[BS * Hh];
__device__ float g_oh[BS * Hh];
__device__ float g_vh[BS * Hh];
__device__ float g_feat[BS * 640];
__device__ float g_Wq[256 * 384];
__device__ float g_Wkv[512 * 384];
__device__ float g_bias_kv[512];
__device__ float g_Waqk[512 * 128];
__device__ float g_bias_aqk[512];
__device__ float g_Wav[256 * 288];
__device__ float g_Wln[256 * 640];
// length sort
__device__ int g_cnt[Ll];
__device__ int g_perm[NSEQ];

__device__ __forceinline__ float sigmoidf_(float x) {
    return __fdividef(1.f, 1.f + __expf(-x));
}
__device__ __forceinline__ float4 tf32_4(float4 v) {
    v.x = wmma::__float_to_tf32(v.x);
    v.y = wmma::__float_to_tf32(v.y);
    v.z = wmma::__float_to_tf32(v.z);
    v.w = wmma::__float_to_tf32(v.w);
    return v;
}
__device__ __forceinline__ void cp16(float* sdst, const float* gsrc) {
    unsigned saddr = (unsigned)__cvta_generic_to_shared(sdst);
    asm volatile("cp.async.cg.shared.global [%0], [%1], 16;\n" :: "r"(saddr), "l"(gsrc));
}
__device__ __forceinline__ void cp_commit() {
    asm volatile("cp.async.commit_group;\n" ::: "memory");
}

// ---------------- fused length sort (one block) ----------------
__global__ void __launch_bounds__(1024) len_sort_all(const int* __restrict__ lenp) {
    __shared__ int bins_s[32], start_s[32], cur_s[32];
    int tid = threadIdx.x;
    if (tid < 32) { bins_s[tid] = 0; cur_s[tid] = 0; }
    __syncthreads();
    for (int i = tid; i < NSEQ; i += 1024) atomicAdd(&bins_s[lenp[i]], 1);
    __syncthreads();
    if (tid == 0) {
        int s = 0;
        for (int l = Ll; l >= 1; l--) { start_s[l] = s; s += bins_s[l]; }
        for (int t = 0; t < Ll; t++) {
            int c = 0;
            for (int l = t + 1; l <= Ll; l++) c += bins_s[l];
            g_cnt[t] = c;
        }
    }
    __syncthreads();
    for (int i = tid; i < NSEQ; i += 1024) {
        int l = lenp[i];
        int pos = start_s[l] + atomicAdd(&cur_s[l], 1);
        g_perm[pos] = i;
    }
}

// ---------------- weight interleaving ----------------
__global__ void prep_whh_i(const float* __restrict__ w_hh, float* __restrict__ dst) {
    int idx = blockIdx.x * blockDim.x + threadIdx.x;
    if (idx >= 768 * 256) return;
    int row = idx >> 8, k = idx & 255;
    int j = row / 3, g = row % 3;
    dst[idx] = w_hh[(g * 256 + j) * 256 + k];
}
__global__ void prep_whhT(const float* __restrict__ w_hh, float* __restrict__ dst) {
    int idx = blockIdx.x * blockDim.x + threadIdx.x;
    if (idx >= 256 * 768) return;
    int k = idx / 768, row = idx % 768;     // coalesced writes
    dst[idx] = w_hh[row * 256 + k];
}
__global__ void prep_wih_i(const float* __restrict__ w_ih, float* __restrict__ dst) {
    int idx = blockIdx.x * blockDim.x + threadIdx.x;
    if (idx >= 768 * 128) return;
    int row = idx >> 7, k = idx & 127;
    int j = row / 3, g = row % 3;
    dst[idx] = w_ih[(g * 256 + j) * 128 + k];
}
__global__ void prep_bias_i(const float* __restrict__ b_ih, const float* __restrict__ b_hh,
                            float* __restrict__ dst) {
    int idx = blockIdx.x * blockDim.x + threadIdx.x;
    if (idx >= 768) return;
    int j = idx / 3, g = idx % 3;
    dst[idx] = b_ih[g * 256 + j];
    dst[768 + idx] = b_hh[g * 256 + j];
}

// ---------------- merged weight padding ----------------
__global__ void pad_all(const float* __restrict__ iq_w, const float* __restrict__ ik_w,
                        const float* __restrict__ iv_w, const float* __restrict__ aq_w,
                        const float* __restrict__ ak_w, const float* __restrict__ av_w,
                        const float* __restrict__ ln_w, const float* __restrict__ ik_b,
                        const float* __restrict__ iv_b, const float* __restrict__ aq_b,
                        const float* __restrict__ ak_b) {
    int idx = blockIdx.x * blockDim.x + threadIdx.x;
    if (idx < 98304) { int n = idx / 384, k = idx % 384; g_Wq[idx] = (k < 383) ? iq_w[n * 383 + k] : 0.f; return; }
    idx -= 98304;
    if (idx < 98304) { int n = idx / 384, k = idx % 384; g_Wkv[idx] = (k < 383) ? ik_w[n * 383 + k] : 0.f; return; }
    idx -= 98304;
    if (idx < 98304) { g_Wkv[98304 + idx] = iv_w[idx]; return; }
    idx -= 98304;
    if (idx < 32768) { int n = idx / 128, k = idx % 128; g_Waqk[idx] = (k < 127) ? aq_w[n * 127 + k] : 0.f; return; }
    idx -= 32768;
    if (idx < 32768) { int n = idx / 128, k = idx % 128; g_Waqk[32768 + idx] = (k < 127) ? ak_w[n * 127 + k] : 0.f; return; }
    idx -= 32768;
    if (idx < 73728) { int n = idx / 288, k = idx % 288; g_Wav[idx] = (k < 257) ? av_w[n * 257 + k] : 0.f; return; }
    idx -= 73728;
    if (idx < 163840) { int n = idx / 640, k = idx % 640; g_Wln[idx] = (k < 639) ? ln_w[n * 639 + k] : 0.f; return; }
    idx -= 163840;
    if (idx < 512) { g_bias_kv[idx] = (idx < 256) ? ik_b[idx] : iv_b[idx - 256]; return; }
    idx -= 512;
    if (idx < 512) g_bias_aqk[idx] = (idx < 256) ? aq_b[idx] : ak_b[idx - 256];
}

// ---------------- merged builders ----------------
__global__ void build_all(const float* __restrict__ inter_r, const float* __restrict__ intra_x) {
    int idx = blockIdx.x * blockDim.x + threadIdx.x;
    if (idx < NSEQ * 384) {
        int i = idx / 384, c = idx % 384;
        g_Mrv[idx] = (c < 256) ? g_his_last[i * 256 + c] : inter_r[i * 128 + (c - 256)];
        return;
    }
    idx -= NSEQ * 384;
    if (idx < BS * 384) {
        int i = idx / 384, c = idx % 384;
        float v;
        if (c < 256) v = g_intra_h[i * 256 + c];
        else if (c < 383) v = intra_x[i * 128 + (c - 256)];
        else v = 0.f;
        g_mpv[idx] = v;
        return;
    }
    idx -= BS * 384;
    if (idx < BS * 257) {
        int i = idx / 257, c = idx % 257;
        g_hp[i * 288 + c] = (c < 256) ? g_intra_h[i * 256 + c] : intra_x[i * 128 + 127];
    }
}

// ---------------- xw projection: tile 96x768 (n0 loop, A L2-resident) --------------
__global__ void __launch_bounds__(256, 2) gemm96_cp(
    const float* __restrict__ A,
    const float* __restrict__ W,
    float* __restrict__ C,
    const int* __restrict__ lenp)
{
    extern __shared__ float sm[];
    const int i0 = blockIdx.x * 96;
    const int tid = threadIdx.x;
    const int warp = tid >> 5;
    const int wy = warp >> 2, wx = warp & 3;

    for (int n0 = 0; n0 < 768; n0 += 192) {
        wmma::fragment<wmma::accumulator, 16, 16, 8, float> acc[3][3];
#pragma unroll
        for (int a = 0; a < 3; a++)
#pragma unroll
            for (int b = 0; b < 3; b++) wmma::fill_fragment(acc[a][b], 0.f);

        auto cp_chunk = [&](int k0, int st) {
            float* As = sm + st * STAGE;
            float* Bs = As + ASZ96;
#pragma unroll
            for (int it = 0; it < 3; it++) {
                int idx = tid + it * 256;
                int r = idx >> 3, k4 = (idx & 7) << 2;
                cp16(As + r * 36 + k4, A + (size_t)(i0 + r) * 128 + k0 + k4);
            }
#pragma unroll
            for (int it = 0; it < 6; it++) {
                int idx = tid + it * 256;
                int rr = idx >> 3, k4 = (idx & 7) << 2;
                cp16(Bs + rr * 36 + k4, W + (size_t)(n0 + rr) * 128 + k0 + k4);
            }
            cp_commit();
        };

        cp_chunk(0, 0);
        for (int s = 0; s < 4; s++) {
            if (s + 1 < 4) {
                cp_chunk((s + 1) * 32, (s + 1) & 1);
                asm volatile("cp.async.wait_group 1;\n" ::: "memory");
            } else {
                asm volatile("cp.async.wait_group 0;\n" ::: "memory");
            }
            __syncthreads();
            float* As = sm + (s & 1) * STAGE;
            float* Bs = As + ASZ96;
#pragma unroll
            for (int kk = 0; kk < 32; kk += 8) {
                wmma::fragment<wmma::matrix_a, 16, 16, 8, wmma::precision::tf32, wmma::row_major> af[3];
                wmma::fragment<wmma::matrix_b, 16, 16, 8, wmma::precision::tf32, wmma::col_major> bf[3];
#pragma unroll
                for (int fy = 0; fy < 3; fy++)
                    wmma::load_matrix_sync(af[fy], As + (wy * 48 + fy * 16) * 36 + kk, 36);
#pragma unroll
                for (int fx = 0; fx < 3; fx++)
                    wmma::load_matrix_sync(bf[fx], Bs + (wx * 48 + fx * 16) * 36 + kk, 36);
#pragma unroll
                for (int fy = 0; fy < 3; fy++)
#pragma unroll
                    for (int fx = 0; fx < 3; fx++)
                        wmma::mma_sync(acc[fy][fx], af[fy], bf[fx], acc[fy][fx]);
            }
            __syncthreads();
        }

        float* Cs = sm;
#pragma unroll
        for (int fy = 0; fy < 3; fy++)
#pragma unroll
            for (int fx = 0; fx < 3; fx++)
                wmma::store_matrix_sync(Cs + (wy * 48 + fy * 16) * 196 + wx * 48 + fx * 16,
                                        acc[fy][fx], 196, wmma::mem_row_major);
        __syncthreads();
#pragma unroll
        for (int it = 0; it < 18; it++) {
            int idx = tid + it * 256;
            int row = idx / 48, c4 = (idx % 48) << 2;
            int grow = i0 + row;
            int seq = grow / Ll, tt = grow - seq * Ll;
            if (tt >= lenp[seq]) continue;
            float4 v = *(float4*)(Cs + row * 196 + c4);
            *(float4*)(C + (size_t)grow * 768 + n0 + c4) = v;
        }
        __syncthreads();
    }
}

// ---------------- fused recurrent GEMM + gate: tile 96x96, 128 thr, 4 blk/SM -------
__global__ void __launch_bounds__(128, 4) gru_step96(
    int t,
    const float* __restrict__ Whh,
    const float* __restrict__ xw,
    const float* __restrict__ bias_i,
    const int* __restrict__ lenp,
    const int* __restrict__ perm,
    const int* __restrict__ cnt,
    const float* __restrict__ h_prev, float* __restrict__ h_out,
    float* __restrict__ his_last)
{
    extern __shared__ float sm[];
    __shared__ int perm_s[96];
    __shared__ int len_s[96];

    const int i0 = blockIdx.x * 96;
    if (i0 >= cnt[t]) return;

    const int n0 = blockIdx.y * 96;
    const int tid = threadIdx.x;
    const int warp = tid >> 5;
    const int wy = warp >> 1, wx = warp & 1;

    if (tid < 96) {
        int p = perm[i0 + tid];
        perm_s[tid] = p;
        len_s[tid] = lenp[p];
    }

    wmma::fragment<wmma::accumulator, 16, 16, 8, float> acc[3][3];
#pragma unroll
    for (int a = 0; a < 3; a++)
#pragma unroll
        for (int b = 0; b < 3; b++) wmma::fill_fragment(acc[a][b], 0.f);

    if (t > 0) {
        auto cp_chunk = [&](int k0, int st) {
            float* As = sm + st * GSTG;
            float* Bs = As + 96 * 36;
#pragma unroll
            for (int it = 0; it < 6; it++) {
                int idx = tid + it * 128;
                int r = idx >> 3, k4 = (idx & 7) << 2;
                cp16(As + r * 36 + k4, h_prev + (size_t)(i0 + r) * 256 + k0 + k4);
            }
#pragma unroll
            for (int it = 0; it < 6; it++) {
                int idx = tid + it * 128;
                int rr = idx >> 3, k4 = (idx & 7) << 2;
                cp16(Bs + rr * 36 + k4, Whh + (size_t)(n0 + rr) * 256 + k0 + k4);
            }
            cp_commit();
        };

        cp_chunk(0, 0);
        for (int s = 0; s < 8; s++) {
            if (s + 1 < 8) {
                cp_chunk((s + 1) * 32, (s + 1) & 1);
                asm volatile("cp.async.wait_group 1;\n" ::: "memory");
            } else {
                asm volatile("cp.async.wait_group 0;\n" ::: "memory");
            }
            __syncthreads();
            float* As = sm + (s & 1) * GSTG;
            float* Bs = As + 96 * 36;
#pragma unroll
            for (int kk = 0; kk < 32; kk += 8) {
                wmma::fragment<wmma::matrix_a, 16, 16, 8, wmma::precision::tf32, wmma::row_major> af[3];
                wmma::fragment<wmma::matrix_b, 16, 16, 8, wmma::precision::tf32, wmma::col_major> bf[3];
#pragma unroll
                for (int fy = 0; fy < 3; fy++)
                    wmma::load_matrix_sync(af[fy], As + (wy * 48 + fy * 16) * 36 + kk, 36);
#pragma unroll
                for (int fx = 0; fx < 3; fx++)
                    wmma::load_matrix_sync(bf[fx], Bs + (wx * 48 + fx * 16) * 36 + kk, 36);
#pragma unroll
                for (int fy = 0; fy < 3; fy++)
#pragma unroll
                    for (int fx = 0; fx < 3; fx++)
                        wmma::mma_sync(acc[fy][fx], af[fy], bf[fx], acc[fy][fx]);
            }
            __syncthreads();
        }
    }

    // ---- single-pass gate epilogue via Cs[96][100]
    float* Cs = sm;
    __syncthreads();
#pragma unroll
    for (int fy = 0; fy < 3; fy++)
#pragma unroll
        for (int fx = 0; fx < 3; fx++)
            wmma::store_matrix_sync(Cs + (wy * 48 + fy * 16) * 100 + wx * 48 + fx * 16,
                                    acc[fy][fx], 100, wmma::mem_row_major);
    __syncthreads();

#pragma unroll
    for (int it = 0; it < 6; it++) {
        int idx = tid + it * 128;
        int row = idx >> 3;
        int q = idx & 7;
        int gi = i0 + row;
        int orig = perm_s[row];
        int c = q * 12;
        int j = blockIdx.y * 32 + q * 4;

        float GH[12], XW[12], BI[12], BH[12];
        *(float4*)&GH[0] = *(float4*)(Cs + row * 100 + c);
        *(float4*)&GH[4] = *(float4*)(Cs + row * 100 + c + 4);
        *(float4*)&GH[8] = *(float4*)(Cs + row * 100 + c + 8);
        const float* xwrow = xw + ((size_t)orig * Ll + t) * 768 + n0 + c;
        *(float4*)&XW[0] = *(const float4*)(xwrow);
        *(float4*)&XW[4] = *(const float4*)(xwrow + 4);
        *(float4*)&XW[8] = *(const float4*)(xwrow + 8);
        *(float4*)&BI[0] = *(const float4*)(bias_i + n0 + c);
        *(float4*)&BI[4] = *(const float4*)(bias_i + n0 + c + 4);
        *(float4*)&BI[8] = *(const float4*)(bias_i + n0 + c + 8);
        *(float4*)&BH[0] = *(const float4*)(bias_i + 768 + n0 + c);
        *(float4*)&BH[4] = *(const float4*)(bias_i + 768 + n0 + c + 4);
        *(float4*)&BH[8] = *(const float4*)(bias_i + 768 + n0 + c + 8);

        float4 hp = make_float4(0.f, 0.f, 0.f, 0.f);
        if (t > 0) hp = *(const float4*)(h_prev + (size_t)gi * 256 + j);
        float hps[4] = {hp.x, hp.y, hp.z, hp.w};
        float hn[4];
#pragma unroll
        for (int u = 0; u < 4; u++) {
            float r = sigmoidf_(XW[3 * u] + BI[3 * u] + GH[3 * u] + BH[3 * u]);
            float z = sigmoidf_(XW[3 * u + 1] + BI[3 * u + 1] + GH[3 * u + 1] + BH[3 * u + 1]);
            float n = tanhf(XW[3 * u + 2] + BI[3 * u + 2] + r * (GH[3 * u + 2] + BH[3 * u + 2]));
            hn[u] = (1.f - z) * n + z * hps[u];
        }
        float4 hv = make_float4(hn[0], hn[1], hn[2], hn[3]);
        *(float4*)(h_out + (size_t)gi * 256 + j) = hv;
        if (len_s[row] == t + 1)
            *(float4*)(his_last + (size_t)orig * 256 + j) = hv;
    }
}

// ---------------- wide tf32 GEMM (intra xw): tile 64x192 ---------------------------
__global__ void __launch_bounds__(256, 2) gemm_tc_wide(
    int M, int K,
    const float* __restrict__ A, int lda,
    const float* __restrict__ W, int ldw,
    float* __restrict__ C, int ldc)
{
    __shared__ float smem[64 * 36 + 192 * 36];
    float* As = smem;
    float* Bs = smem + 64 * 36;
    float* Cs = smem;

    int i0 = blockIdx.x * 64, n0 = blockIdx.y * 192;
    int tid = threadIdx.x;
    int warp = tid >> 5, wy = warp >> 2, wx = warp & 3;

    wmma::fragment<wmma::accumulator, 16, 16, 8, float> acc[2][3];
#pragma unroll
    for (int a = 0; a < 2; a++)
#pragma unroll
        for (int b = 0; b < 3; b++) wmma::fill_fragment(acc[a][b], 0.f);

    float4 ra[2], rb[6];
    auto ldchunk = [&](int k0) {
#pragma unroll
        for (int it = 0; it < 2; it++) {
            int idx = tid + it * 256;
            int r = idx >> 3, k4 = (idx & 7) << 2;
            float4 v = make_float4(0.f, 0.f, 0.f, 0.f);
            if (i0 + r < M) v = *(const float4*)(A + (size_t)(i0 + r) * lda + k0 + k4);
            ra[it] = v;
        }
#pragma unroll
        for (int it = 0; it < 6; it++) {
            int idx = tid + it * 256;
            int c = idx >> 3, k4 = (idx & 7) << 2;
            rb[it] = *(const float4*)(W + (size_t)(n0 + c) * ldw + k0 + k4);
        }
    };
    auto stchunk = [&]() {
#pragma unroll
        for (int it = 0; it < 2; it++) {
            int idx = tid + it * 256;
            int r = idx >> 3, k4 = (idx & 7) << 2;
            *(float4*)(As + r * 36 + k4) = tf32_4(ra[it]);
        }
#pragma unroll
        for (int it = 0; it < 6; it++) {
            int idx = tid + it * 256;
            int c = idx >> 3, k4 = (idx & 7) << 2;
            *(float4*)(Bs + c * 36 + k4) = tf32_4(rb[it]);
        }
    };

    ldchunk(0); stchunk(); __syncthreads();
    for (int k0 = 0; k0 < K; k0 += 32) {
        bool more = (k0 + 32) < K;
        if (more) ldchunk(k0 + 32);
#pragma unroll
        for (int kk = 0; kk < 32; kk += 8) {
            wmma::fragment<wmma::matrix_a, 16, 16, 8, wmma::precision::tf32, wmma::row_major> af[2];
            wmma::fragment<wmma::matrix_b, 16, 16, 8, wmma::precision::tf32, wmma::col_major> bf[3];
#pragma unroll
            for (int fy = 0; fy < 2; fy++)
                wmma::load_matrix_sync(af[fy], As + (wy * 32 + fy * 16) * 36 + kk, 36);
#pragma unroll
            for (int fx = 0; fx < 3; fx++)
                wmma::load_matrix_sync(bf[fx], Bs + (wx * 48 + fx * 16) * 36 + kk, 36);
#pragma unroll
            for (int fy = 0; fy < 2; fy++)
#pragma unroll
                for (int fx = 0; fx < 3; fx++)
                    wmma::mma_sync(acc[fy][fx], af[fy], bf[fx], acc[fy][fx]);
        }
        __syncthreads();
        if (more) { stchunk(); __syncthreads(); }
    }

    for (int pass = 0; pass < 2; pass++) {
        __syncthreads();
        if (wy == pass) {
#pragma unroll
            for (int fy = 0; fy < 2; fy++)
#pragma unroll
                for (int fx = 0; fx < 3; fx++)
                    wmma::store_matrix_sync(Cs + (fy * 16) * 196 + wx * 48 + fx * 16,
                                            acc[fy][fx], 196, wmma::mem_row_major);
        }
        __syncthreads();
#pragma unroll
        for (int it = 0; it < 6; it++) {
            int idx = tid + it * 256;
            int row = idx / 48, c4 = (idx % 48) << 2;
            int gi = i0 + pass * 32 + row;
            if (gi >= M) continue;
            float4 v = *(float4*)(Cs + row * 196 + c4);
            *(float4*)(C + (size_t)gi * ldc + n0 + c4) = v;
        }
    }
}

// ---------------- tf32 GEMM (tile 128x64): C = A @ W^T + bias ----------------------
__global__ void __launch_bounds__(256, 2) gemm_tc(
    int M, int N, int K,
    const float* __restrict__ A, int lda,
    const float* __restrict__ W, int ldw,
    const float* __restrict__ bias,
    float* __restrict__ C, int ldc)
{
    __shared__ float smem[128 * 68];
    float* As = smem;
    float* Bs = smem + 128 * 40;

    int i0 = blockIdx.x * 128, n0 = blockIdx.y * 64;
    int tid = threadIdx.x;
    int warp = tid >> 5;
    int wy = warp >> 1, wx = warp & 1;

    wmma::fragment<wmma::accumulator, 16, 16, 8, float> acc[2][2];
#pragma unroll
    for (int a = 0; a < 2; a++)
#pragma unroll
        for (int b = 0; b < 2; b++) wmma::fill_fragment(acc[a][b], 0.f);

    float4 ra[4], rb[2];
    auto ldchunk = [&](int k0) {
#pragma unroll
        for (int it = 0; it < 4; it++) {
            int idx = tid + it * 256;
            int r = idx >> 3, k4 = (idx & 7) << 2;
            float4 v = make_float4(0.f, 0.f, 0.f, 0.f);
            int gi = i0 + r;
            if (gi < M) v = *(const float4*)(A + (size_t)gi * lda + k0 + k4);
            ra[it] = v;
        }
#pragma unroll
        for (int it = 0; it < 2; it++) {
            int idx = tid + it * 256;
            int n = idx >> 3, k4 = (idx & 7) << 2;
            rb[it] = *(const float4*)(W + (size_t)(n0 + n) * ldw + k0 + k4);
        }
    };
    auto stchunk = [&]() {
#pragma unroll
        for (int it = 0; it < 4; it++) {
            int idx = tid + it * 256;
            int r = idx >> 3, k4 = (idx & 7) << 2;
            *(float4*)(As + r * 40 + k4) = tf32_4(ra[it]);
        }
#pragma unroll
        for (int it = 0; it < 2; it++) {
            int idx = tid + it * 256;
            int n = idx >> 3, k4 = (idx & 7) << 2;
            *(float4*)(Bs + n * 40 + k4) = tf32_4(rb[it]);
        }
    };

    ldchunk(0); stchunk(); __syncthreads();
    for (int k0 = 0; k0 < K; k0 += 32) {
        bool more = (k0 + 32) < K;
        if (more) ldchunk(k0 + 32);
#pragma unroll
        for (int kk = 0; kk < 32; kk += 8) {
            wmma::fragment<wmma::matrix_a, 16, 16, 8, wmma::precision::tf32, wmma::row_major> af[2];
            wmma::fragment<wmma::matrix_b, 16, 16, 8, wmma::precision::tf32, wmma::col_major> bf[2];
#pragma unroll
            for (int fy = 0; fy < 2; fy++)
                wmma::load_matrix_sync(af[fy], As + (wy * 32 + fy * 16) * 40 + kk, 40);
#pragma unroll
            for (int fx = 0; fx < 2; fx++)
                wmma::load_matrix_sync(bf[fx], Bs + (wx * 32 + fx * 16) * 40 + kk, 40);
#pragma unroll
            for (int fy = 0; fy < 2; fy++)
#pragma unroll
                for (int fx = 0; fx < 2; fx++)
                    wmma::mma_sync(acc[fy][fx], af[fy], bf[fx], acc[fy][fx]);
        }
        __syncthreads();
        if (more) { stchunk(); __syncthreads(); }
    }

    float* Cs = smem;
#pragma unroll
    for (int fy = 0; fy < 2; fy++)
#pragma unroll
        for (int fx = 0; fx < 2; fx++)
            wmma::store_matrix_sync(Cs + (wy * 32 + fy * 16) * 68 + wx * 32 + fx * 16,
                                    acc[fy][fx], 68, wmma::mem_row_major);
    __syncthreads();
#pragma unroll
    for (int it = 0; it < 8; it++) {
        int idx = tid + it * 256;
        int r = idx >> 4, c4 = (idx & 15) << 2;
        int gi = i0 + r;
        if (gi >= M) continue;
        float4 v = *(float4*)(Cs + r * 68 + c4);
        if (bias) {
            v.x += bias[n0 + c4];     v.y += bias[n0 + c4 + 1];
            v.z += bias[n0 + c4 + 2]; v.w += bias[n0 + c4 + 3];
        }
        *(float4*)(C + (size_t)gi * ldc + n0 + c4) = v;
    }
}

// ---------------- fused intra GRU: coalesced transposed weights --------------------
// Thread tid owns gate-row tid. Per k: warp reads 32 consecutive floats of
// w_hhT[k*768 + tid] (one 128B line, was 32 lines before); h_sh[k] is an LDS
// broadcast. 4 accumulators break the FMA dependency chain.
__global__ void __launch_bounds__(768) intra_gru(
    const float* __restrict__ xw_intra,
    const float* __restrict__ w_hhT,          // [256][768]
    const float* __restrict__ b_ih, const float* __restrict__ b_hh,
    float* __restrict__ intra_h)
{
    int b = blockIdx.x;
    int tid = threadIdx.x;
    __shared__ float h_sh[256];
    __shared__ float gh_sh[768];
    if (tid < 256) h_sh[tid] = 0.f;
    __syncthreads();
    for (int t = 0; t < Ss; t++) {
        float a0 = 0.f, a1 = 0.f, a2 = 0.f, a3 = 0.f;
#pragma unroll 16
        for (int k = 0; k < 256; k += 4) {
            a0 += w_hhT[(size_t)(k + 0) * 768 + tid] * h_sh[k + 0];
            a1 += w_hhT[(size_t)(k + 1) * 768 + tid] * h_sh[k + 1];
            a2 += w_hhT[(size_t)(k + 2) * 768 + tid] * h_sh[k + 2];
            a3 += w_hhT[(size_t)(k + 3) * 768 + tid] * h_sh[k + 3];
        }
        gh_sh[tid] = (a0 + a1) + (a2 + a3);
        __syncthreads();
        if (tid < 256) {
            const float* xwrow = xw_intra + ((size_t)b * Ss + t) * 768;
            float r = sigmoidf_(xwrow[3 * tid] + b_ih[tid] + gh_sh[tid] + b_hh[tid]);
            float z = sigmoidf_(xwrow[3 * tid + 1] + b_ih[256 + tid] + gh_sh[256 + tid] + b_hh[256 + tid]);
            float n = tanhf(xwrow[3 * tid + 2] + b_ih[512 + tid] + r * (gh_sh[512 + tid] + b_hh[512 + tid]));
            float hn = (1.f - z) * n + z * h_sh[tid];
            h_sh[tid] = hn;
            intra_h[((size_t)b * Ss + t) * 256 + tid] = hn;
        }
        __syncthreads();
    }
}

// ---------------- build_feat ----------------
__global__ void build_feat(const float* __restrict__ intra_x, const float* __restrict__ wr,
                           const float* __restrict__ vv, const float* __restrict__ vh,
                           const float* __restrict__ intra_h, float* __restrict__ feat) {
    int idx = blockIdx.x * blockDim.x + threadIdx.x;
    if (idx >= BS * 640) return;
    float e0 = expf(wr[0]), e1 = expf(wr[1]);
    float w0 = e0 / (e0 + e1), w1 = 1.f - w0;
    int i = idx / 640, c = idx % 640;
    float v;
    if (c < 256) v = w0 * vv[i * 256 + c] + w1 * vh[i * 256 + c];
    else if (c < 512) v = intra_h[i * 256 + (c - 256)];
    else if (c < 639) v = intra_x[i * 128 + (c - 512)];
    else v = 0.f;
    feat[idx] = v;
}

// ---------------- attention cores ----------------
__global__ void __launch_bounds__(256) inter_attn2(
    const float* __restrict__ qi, const float* __restrict__ kvi, float* __restrict__ oi)
{
    int warp = threadIdx.x >> 5, lane = threadIdx.x & 31;
    int item = blockIdx.x * 8 + warp;
    int row = item >> 1, head = item & 1;
    int off = head * 128 + lane * 4;

    float4 q = *(const float4*)(qi + (size_t)row * 256 + off);
    float p[6];
#pragma unroll
    for (int r = 0; r < 6; r++) {
        float4 k4 = *(const float4*)(kvi + (size_t)(row * 6 + r) * 512 + off);
        float d = q.x * k4.x + q.y * k4.y + q.z * k4.z + q.w * k4.w;
#pragma unroll
        for (int o = 16; o; o >>= 1) d += __shfl_xor_sync(0xffffffffu, d, o);
        p[r] = d * 0.08838834764831843f;
    }
    float mx = p[0];
#pragma unroll
    for (int r = 1; r < 6; r++) mx = fmaxf(mx, p[r]);
    float sum = 0.f;
#pragma unroll
    for (int r = 0; r < 6; r++) { p[r] = expf(p[r] - mx); sum += p[r]; }
    float inv = 1.f / sum;
    float4 acc = make_float4(0.f, 0.f, 0.f, 0.f);
#pragma unroll
    for (int r = 0; r < 6; r++) {
        float4 v4 = *(const float4*)(kvi + (size_t)(row * 6 + r) * 512 + 256 + off);
        float w = p[r] * inv;
        acc.x += w * v4.x; acc.y += w * v4.y; acc.z += w * v4.z; acc.w += w * v4.w;
    }
    *(float4*)(oi + (size_t)row * 256 + off) = acc;
}

// intra: block per (head, batch); q/k from fused qkh [row][512] (q at 0, k at 256).
__global__ void __launch_bounds__(256) intra_attn2(
    const float* __restrict__ qkh,
    const float* __restrict__ vhp, float* __restrict__ oh)
{
    extern __shared__ float sm[];
    float* Qs = sm + IA_QS;
    float* Ks = sm + IA_KS;
    float* Vs = sm + IA_VS;
    float* Ps = sm + IA_PS;

    int head = blockIdx.x, b = blockIdx.y;
    int tid = threadIdx.x;

    for (int idx = tid; idx < 64 * 32; idx += 256) {
        int row = idx >> 5, c4 = (idx & 31) << 2;
        size_t gq = (size_t)(b * 64 + row) * 512 + head * 128 + c4;
        size_t gv = (size_t)(b * 64 + row) * 256 + head * 128 + c4;
        *(float4*)(Qs + row * 132 + c4) = *(const float4*)(qkh + gq);
        *(float4*)(Ks + row * 132 + c4) = *(const float4*)(qkh + gq + 256);
        *(float4*)(Vs + row * 132 + c4) = *(const float4*)(vhp + gv);
    }
    __syncthreads();

    for (int idx = tid; idx < 64 * 64; idx += 256) {
        int tq = idx >> 6, tk = idx & 63;
        if (tk > tq) continue;
        const float4* qp = (const float4*)(Qs + tq * 132);
        const float4* kp = (const float4*)(Ks + tk * 132);
        float acc = 0.f;
#pragma unroll
        for (int k = 0; k < 32; k++) {
            float4 a = qp[k], c = kp[k];
            acc += a.x * c.x + a.y * c.y + a.z * c.z + a.w * c.w;
        }
        Ps[tq * 65 + tk] = acc * 0.08838834764831843f;
    }
    __syncthreads();

    if (tid < 64) {
        int tq = tid;
        float mx = -1e30f;
        for (int k = 0; k <= tq; k++) mx = fmaxf(mx, Ps[tq * 65 + k]);
        float sum = 0.f;
        for (int k = 0; k <= tq; k++) { float e = expf(Ps[tq * 65 + k] - mx); Ps[tq * 65 + k] = e; sum += e; }
        float inv = 1.f / sum;
        for (int k = 0; k <= tq; k++) Ps[tq * 65 + k] *= inv;
    }
    __syncthreads();

    for (int idx = tid; idx < 64 * 32; idx += 256) {
        int tq = idx >> 5, d4 = (idx & 31) << 2;
        float4 acc = make_float4(0.f, 0.f, 0.f, 0.f);
        for (int k = 0; k <= tq; k++) {
            float w = Ps[tq * 65 + k];
            float4 v = *(float4*)(Vs + k * 132 + d4);
            acc.x += w * v.x; acc.y += w * v.y; acc.z += w * v.z; acc.w += w * v.w;
        }
        *(float4*)(oh + (size_t)(b * 64 + tq) * 256 + head * 128 + d4) = acc;
    }
}

// ---------------- launch ----------------
extern "C" void kernel_launch(void* const* d_in, const int* in_sizes, int n_in,
                              void* d_out, int out_size) {
    const float* intra_x   = (const float*)d_in[0];
    const float* inter_his = (const float*)d_in[1];
    const float* inter_r   = (const float*)d_in[2];
    const int*   inter_len = (const int*)d_in[4];
    const float* w_ih = (const float*)d_in[5];
    const float* w_hh = (const float*)d_in[6];
    const float* b_ih = (const float*)d_in[7];
    const float* b_hh = (const float*)d_in[8];
    const float* iq_w = (const float*)d_in[9];
    const float* iq_b = (const float*)d_in[10];
    const float* ik_w = (const float*)d_in[11];
    const float* ik_b = (const float*)d_in[12];
    const float* iv_w = (const float*)d_in[13];
    const float* iv_b = (const float*)d_in[14];
    const float* io_w = (const float*)d_in[15];
    const float* io_b = (const float*)d_in[16];
    const float* aq_w = (const float*)d_in[17];
    const float* aq_b = (const float*)d_in[18];
    const float* ak_w = (const float*)d_in[19];
    const float* ak_b = (const float*)d_in[20];
    const float* av_w = (const float*)d_in[21];
    const float* av_b = (const float*)d_in[22];
    const float* ao_w = (const float*)d_in[23];
    const float* ao_b = (const float*)d_in[24];
    const float* wr   = (const float*)d_in[25];
    const float* ln_w = (const float*)d_in[26];
    const float* ln_b = (const float*)d_in[27];
    float* out = (float*)d_out;

    float *p_Whh_i, *p_WhhT, *p_Wih_i, *p_bias_i, *p_xw, *p_xw_intra, *p_hA, *p_hB, *p_his, *p_ih;
    float *p_Mrv, *p_mpv, *p_hp, *p_qi, *p_kvi, *p_oi, *p_vv, *p_qkh, *p_vhp;
    float *p_oh, *p_vh, *p_feat, *p_Wq, *p_Wkv, *p_bias_kv, *p_Waqk, *p_bias_aqk, *p_Wav, *p_Wln;
    int *p_perm, *p_cnt;
    cudaGetSymbolAddress((void**)&p_Whh_i, g_Whh_i);
    cudaGetSymbolAddress((void**)&p_WhhT, g_WhhT);
    cudaGetSymbolAddress((void**)&p_Wih_i, g_Wih_i);
    cudaGetSymbolAddress((void**)&p_bias_i, g_bias_i);
    cudaGetSymbolAddress((void**)&p_xw, g_xw_inter);
    cudaGetSymbolAddress((void**)&p_xw_intra, g_xw_intra);
    cudaGetSymbolAddress((void**)&p_hA, g_hA);
    cudaGetSymbolAddress((void**)&p_hB, g_hB);
    cudaGetSymbolAddress((void**)&p_his, g_his_last);
    cudaGetSymbolAddress((void**)&p_ih, g_intra_h);
    cudaGetSymbolAddress((void**)&p_Mrv, g_Mrv);
    cudaGetSymbolAddress((void**)&p_mpv, g_mpv);
    cudaGetSymbolAddress((void**)&p_hp, g_hp);
    cudaGetSymbolAddress((void**)&p_qi, g_qi);
    cudaGetSymbolAddress((void**)&p_kvi, g_kvi);
    cudaGetSymbolAddress((void**)&p_oi, g_oi);
    cudaGetSymbolAddress((void**)&p_vv, g_vv);
    cudaGetSymbolAddress((void**)&p_qkh, g_qkh);
    cudaGetSymbolAddress((void**)&p_vhp, g_vhp);
    cudaGetSymbolAddress((void**)&p_oh, g_oh);
    cudaGetSymbolAddress((void**)&p_vh, g_vh);
    cudaGetSymbolAddress((void**)&p_feat, g_feat);
    cudaGetSymbolAddress((void**)&p_Wq, g_Wq);
    cudaGetSymbolAddress((void**)&p_Wkv, g_Wkv);
    cudaGetSymbolAddress((void**)&p_bias_kv, g_bias_kv);
    cudaGetSymbolAddress((void**)&p_Waqk, g_Waqk);
    cudaGetSymbolAddress((void**)&p_bias_aqk, g_bias_aqk);
    cudaGetSymbolAddress((void**)&p_Wav, g_Wav);
    cudaGetSymbolAddress((void**)&p_Wln, g_Wln);
    cudaGetSymbolAddress((void**)&p_perm, g_perm);
    cudaGetSymbolAddress((void**)&p_cnt, g_cnt);

    static bool attr_set = false;
    if (!attr_set) {
        cudaFuncSetAttribute(gemm96_cp, cudaFuncAttributeMaxDynamicSharedMemorySize, SMEMF * 4);
        cudaFuncSetAttribute(gru_step96, cudaFuncAttributeMaxDynamicSharedMemorySize, GSMEMF * 4);
        cudaFuncSetAttribute(intra_attn2, cudaFuncAttributeMaxDynamicSharedMemorySize, IA_FLOATS * 4);
        attr_set = true;
    }

    // prep
    len_sort_all<<<1, 1024>>>(inter_len);
    prep_whh_i<<<(768 * 256 + 255) / 256, 256>>>(w_hh, p_Whh_i);
    prep_bias_i<<<3, 256>>>(b_ih, b_hh, p_bias_i);
    prep_wih_i<<<(768 * 128 + 255) / 256, 256>>>(w_ih, p_Wih_i);
    prep_whhT<<<(256 * 768 + 255) / 256, 256>>>(w_hh, p_WhhT);

    // hoisted inter input projection (n0-looped, len-guarded stores)
    gemm96_cp<<<NROWS_XW / 96, 256, SMEMF * 4>>>(inter_his, p_Wih_i, p_xw, inter_len);

    // inter GRU chain (len-pruned, permuted space; 96x96 tiles, 4 blocks/SM)
    for (int t = 0; t < Ll; t++) {
        float* h_out  = (t & 1) ? p_hB : p_hA;
        float* h_prev = (t & 1) ? p_hA : p_hB;
        gru_step96<<<dim3(NSEQ / 96, 8), 128, GSMEMF * 4>>>(t, p_Whh_i, p_xw, p_bias_i,
                                                            inter_len, p_perm, p_cnt,
                                                            h_prev, h_out, p_his);
    }

    // intra path (coalesced recurrence)
    gemm_tc_wide<<<dim3(16, 4), 256>>>(BS, 128, intra_x, 128, p_Wih_i, 128, p_xw_intra, 768);
    intra_gru<<<Bb, 768>>>(p_xw_intra, p_WhhT, b_ih, b_hh, p_ih);

    // merged weight padding + builders
    pad_all<<<(599040 + 255) / 256, 256>>>(iq_w, ik_w, iv_w, aq_w, ak_w, av_w, ln_w,
                                           ik_b, iv_b, aq_b, ak_b);
    build_all<<<(3015680 + 255) / 256, 256>>>(inter_r, intra_x);

    // inter MHA (K/V fused into one N=512 GEMM)
    gemm_tc<<<dim3(8, 4), 256>>>(BS, 256, 384, p_mpv, 384, p_Wq, 384, iq_b, p_qi, 256);
    gemm_tc<<<dim3(48, 8), 256>>>(NSEQ, 512, 384, p_Mrv, 384, p_Wkv, 384, p_bias_kv, p_kvi, 512);
    inter_attn2<<<256, 256>>>(p_qi, p_kvi, p_oi);
    gemm_tc<<<dim3(8, 4), 256>>>(BS, 256, 256, p_oi, 256, io_w, 256, io_b, p_vv, 256);

    // intra MHA (q+k fused into one N=512 GEMM)
    gemm_tc<<<dim3(8, 8), 256>>>(BS, 512, 128, intra_x, 128, p_Waqk, 128, p_bias_aqk, p_qkh, 512);
    gemm_tc<<<dim3(8, 4), 256>>>(BS, 256, 288, p_hp, 288, p_Wav, 288, av_b, p_vhp, 256);
    intra_attn2<<<dim3(2, 16), 256, IA_FLOATS * 4>>>(p_qkh, p_vhp, p_oh);
    gemm_tc<<<dim3(8, 4), 256>>>(BS, 256, 256, p_oh, 256, ao_w, 256, ao_b, p_vh, 256);

    // combine + final projection
    build_feat<<<(BS * 640 + 255) / 256, 256>>>(intra_x, wr, p_vv, p_vh, p_ih, p_feat);
    gemm_tc<<<dim3(8, 4), 256>>>(BS, 256, 640, p_feat, 640, p_Wln, 640, ln_b, out, 256);
}

// round 16
// speedup vs baseline: 2.3491x; 1.2814x over previous
#include <cuda_runtime.h>
#include <mma.h>
#include <math.h>
using namespace nvcuda;

// Problem dims
#define Bb 16
#define Ss 64
#define Rr 6
#define Ll 24
#define Dd 128
#define Hh 256
#define BS 1024      // B*S
#define NSEQ 6144    // B*S*R
#define NROWS_XW (NSEQ * Ll)   // 147456

// smem stage geometry for gemm96_cp (floats)
#define ASZ96 (96 * 36)        // 3456
#define BSZ   (192 * 36)       // 6912
#define STAGE (ASZ96 + BSZ)    // 10368
#define SMEMF (2 * STAGE)      // 20736 floats = 82944 B

// gru_step96 small-tile stage geometry (floats)
#define GSTG (96 * 36 + 96 * 36)     // 6912 per stage
#define GSMEMF (2 * GSTG)            // 13824 floats = 55296 B

// intra_attn smem layout (floats)
#define IA_QS 0
#define IA_KS 8448
#define IA_VS 16896
#define IA_PS 25344
#define IA_FLOATS 29504

// ---------------- scratch (device globals; no allocations allowed) ----------------
__device__ float g_Whh_i[768 * 256];
__device__ float g_WhhT[256 * 768];     // transposed: [k][row] for coalesced intra_gru
__device__ float g_Wih_i[768 * 128];
__device__ float g_bias_i[2 * 768];
__device__ float g_xw_inter[(size_t)NROWS_XW * 768];
__device__ float g_xw_intra[BS * 768];
__device__ float g_hA[NSEQ * Hh];
__device__ float g_hB[NSEQ * Hh];
__device__ float g_his_last[NSEQ * Hh];
__device__ float g_intra_h[BS * Hh];
__device__ float g_Mrv[NSEQ * 384];
__device__ float g_mpv[BS * 384];
__device__ float g_hp[BS * 288];
__device__ float g_qi[BS * Hh];
__device__ float g_kvi[NSEQ * 512];
__device__ float g_oi[BS * Hh];
__device__ float g_vv[BS * Hh];
__device__ float g_qkh[BS * 512];       // fused intra q|k projections
__device__ float g_vhp[BS * Hh];
__device__ float g_oh[BS * Hh];
__device__ float g_vh[BS * Hh];
__device__ float g_feat[BS * 640];
__device__ float g_Wq[256 * 384];
__device__ float g_Wkv[512 * 384];
__device__ float g_bias_kv[512];
__device__ float g_Waqk[512 * 128];
__device__ float g_bias_aqk[512];
__device__ float g_Wav[256 * 288];
__device__ float g_Wln[256 * 640];
// length sort
__device__ int g_cnt[Ll];
__device__ int g_perm[NSEQ];

__device__ __forceinline__ float sigmoidf_(float x) {
    return __fdividef(1.f, 1.f + __expf(-x));
}
__device__ __forceinline__ float4 tf32_4(float4 v) {
    v.x = wmma::__float_to_tf32(v.x);
    v.y = wmma::__float_to_tf32(v.y);
    v.z = wmma::__float_to_tf32(v.z);
    v.w = wmma::__float_to_tf32(v.w);
    return v;
}
__device__ __forceinline__ void cp16(float* sdst, const float* gsrc) {
    unsigned saddr = (unsigned)__cvta_generic_to_shared(sdst);
    asm volatile("cp.async.cg.shared.global [%0], [%1], 16;\n" :: "r"(saddr), "l"(gsrc));
}
__device__ __forceinline__ void cp_commit() {
    asm volatile("cp.async.commit_group;\n" ::: "memory");
}

// ---------------- fused length sort (one block) ----------------
__global__ void __launch_bounds__(1024) len_sort_all(const int* __restrict__ lenp) {
    __shared__ int bins_s[32], start_s[32], cur_s[32];
    int tid = threadIdx.x;
    if (tid < 32) { bins_s[tid] = 0; cur_s[tid] = 0; }
    __syncthreads();
    for (int i = tid; i < NSEQ; i += 1024) atomicAdd(&bins_s[lenp[i]], 1);
    __syncthreads();
    if (tid == 0) {
        int s = 0;
        for (int l = Ll; l >= 1; l--) { start_s[l] = s; s += bins_s[l]; }
        for (int t = 0; t < Ll; t++) {
            int c = 0;
            for (int l = t + 1; l <= Ll; l++) c += bins_s[l];
            g_cnt[t] = c;
        }
    }
    __syncthreads();
    for (int i = tid; i < NSEQ; i += 1024) {
        int l = lenp[i];
        int pos = start_s[l] + atomicAdd(&cur_s[l], 1);
        g_perm[pos] = i;
    }
}

// ---------------- weight interleaving ----------------
__global__ void prep_whh_i(const float* __restrict__ w_hh, float* __restrict__ dst) {
    int idx = blockIdx.x * blockDim.x + threadIdx.x;
    if (idx >= 768 * 256) return;
    int row = idx >> 8, k = idx & 255;
    int j = row / 3, g = row % 3;
    dst[idx] = w_hh[(g * 256 + j) * 256 + k];
}
__global__ void prep_whhT(const float* __restrict__ w_hh, float* __restrict__ dst) {
    int idx = blockIdx.x * blockDim.x + threadIdx.x;
    if (idx >= 256 * 768) return;
    int k = idx / 768, row = idx % 768;     // coalesced writes
    dst[idx] = w_hh[row * 256 + k];
}
__global__ void prep_wih_i(const float* __restrict__ w_ih, float* __restrict__ dst) {
    int idx = blockIdx.x * blockDim.x + threadIdx.x;
    if (idx >= 768 * 128) return;
    int row = idx >> 7, k = idx & 127;
    int j = row / 3, g = row % 3;
    dst[idx] = w_ih[(g * 256 + j) * 128 + k];
}
__global__ void prep_bias_i(const float* __restrict__ b_ih, const float* __restrict__ b_hh,
                            float* __restrict__ dst) {
    int idx = blockIdx.x * blockDim.x + threadIdx.x;
    if (idx >= 768) return;
    int j = idx / 3, g = idx % 3;
    dst[idx] = b_ih[g * 256 + j];
    dst[768 + idx] = b_hh[g * 256 + j];
}

// ---------------- merged weight padding ----------------
__global__ void pad_all(const float* __restrict__ iq_w, const float* __restrict__ ik_w,
                        const float* __restrict__ iv_w, const float* __restrict__ aq_w,
                        const float* __restrict__ ak_w, const float* __restrict__ av_w,
                        const float* __restrict__ ln_w, const float* __restrict__ ik_b,
                        const float* __restrict__ iv_b, const float* __restrict__ aq_b,
                        const float* __restrict__ ak_b) {
    int idx = blockIdx.x * blockDim.x + threadIdx.x;
    if (idx < 98304) { int n = idx / 384, k = idx % 384; g_Wq[idx] = (k < 383) ? iq_w[n * 383 + k] : 0.f; return; }
    idx -= 98304;
    if (idx < 98304) { int n = idx / 384, k = idx % 384; g_Wkv[idx] = (k < 383) ? ik_w[n * 383 + k] : 0.f; return; }
    idx -= 98304;
    if (idx < 98304) { g_Wkv[98304 + idx] = iv_w[idx]; return; }
    idx -= 98304;
    if (idx < 32768) { int n = idx / 128, k = idx % 128; g_Waqk[idx] = (k < 127) ? aq_w[n * 127 + k] : 0.f; return; }
    idx -= 32768;
    if (idx < 32768) { int n = idx / 128, k = idx % 128; g_Waqk[32768 + idx] = (k < 127) ? ak_w[n * 127 + k] : 0.f; return; }
    idx -= 32768;
    if (idx < 73728) { int n = idx / 288, k = idx % 288; g_Wav[idx] = (k < 257) ? av_w[n * 257 + k] : 0.f; return; }
    idx -= 73728;
    if (idx < 163840) { int n = idx / 640, k = idx % 640; g_Wln[idx] = (k < 639) ? ln_w[n * 639 + k] : 0.f; return; }
    idx -= 163840;
    if (idx < 512) { g_bias_kv[idx] = (idx < 256) ? ik_b[idx] : iv_b[idx - 256]; return; }
    idx -= 512;
    if (idx < 512) g_bias_aqk[idx] = (idx < 256) ? aq_b[idx] : ak_b[idx - 256];
}

// ---------------- merged builders ----------------
__global__ void build_all(const float* __restrict__ inter_r, const float* __restrict__ intra_x) {
    int idx = blockIdx.x * blockDim.x + threadIdx.x;
    if (idx < NSEQ * 384) {
        int i = idx / 384, c = idx % 384;
        g_Mrv[idx] = (c < 256) ? g_his_last[i * 256 + c] : inter_r[i * 128 + (c - 256)];
        return;
    }
    idx -= NSEQ * 384;
    if (idx < BS * 384) {
        int i = idx / 384, c = idx % 384;
        float v;
        if (c < 256) v = g_intra_h[i * 256 + c];
        else if (c < 383) v = intra_x[i * 128 + (c - 256)];
        else v = 0.f;
        g_mpv[idx] = v;
        return;
    }
    idx -= BS * 384;
    if (idx < BS * 257) {
        int i = idx / 257, c = idx % 257;
        g_hp[i * 288 + c] = (c < 256) ? g_intra_h[i * 256 + c] : intra_x[i * 128 + 127];
    }
}

// ---------------- xw projection: tile 96x768 (n0 loop, A L2-resident) --------------
__global__ void __launch_bounds__(256, 2) gemm96_cp(
    const float* __restrict__ A,
    const float* __restrict__ W,
    float* __restrict__ C,
    const int* __restrict__ lenp)
{
    extern __shared__ float sm[];
    const int i0 = blockIdx.x * 96;
    const int tid = threadIdx.x;
    const int warp = tid >> 5;
    const int wy = warp >> 2, wx = warp & 3;

    for (int n0 = 0; n0 < 768; n0 += 192) {
        wmma::fragment<wmma::accumulator, 16, 16, 8, float> acc[3][3];
#pragma unroll
        for (int a = 0; a < 3; a++)
#pragma unroll
            for (int b = 0; b < 3; b++) wmma::fill_fragment(acc[a][b], 0.f);

        auto cp_chunk = [&](int k0, int st) {
            float* As = sm + st * STAGE;
            float* Bs = As + ASZ96;
#pragma unroll
            for (int it = 0; it < 3; it++) {
                int idx = tid + it * 256;
                int r = idx >> 3, k4 = (idx & 7) << 2;
                cp16(As + r * 36 + k4, A + (size_t)(i0 + r) * 128 + k0 + k4);
            }
#pragma unroll
            for (int it = 0; it < 6; it++) {
                int idx = tid + it * 256;
                int rr = idx >> 3, k4 = (idx & 7) << 2;
                cp16(Bs + rr * 36 + k4, W + (size_t)(n0 + rr) * 128 + k0 + k4);
            }
            cp_commit();
        };

        cp_chunk(0, 0);
        for (int s = 0; s < 4; s++) {
            if (s + 1 < 4) {
                cp_chunk((s + 1) * 32, (s + 1) & 1);
                asm volatile("cp.async.wait_group 1;\n" ::: "memory");
            } else {
                asm volatile("cp.async.wait_group 0;\n" ::: "memory");
            }
            __syncthreads();
            float* As = sm + (s & 1) * STAGE;
            float* Bs = As + ASZ96;
#pragma unroll
            for (int kk = 0; kk < 32; kk += 8) {
                wmma::fragment<wmma::matrix_a, 16, 16, 8, wmma::precision::tf32, wmma::row_major> af[3];
                wmma::fragment<wmma::matrix_b, 16, 16, 8, wmma::precision::tf32, wmma::col_major> bf[3];
#pragma unroll
                for (int fy = 0; fy < 3; fy++)
                    wmma::load_matrix_sync(af[fy], As + (wy * 48 + fy * 16) * 36 + kk, 36);
#pragma unroll
                for (int fx = 0; fx < 3; fx++)
                    wmma::load_matrix_sync(bf[fx], Bs + (wx * 48 + fx * 16) * 36 + kk, 36);
#pragma unroll
                for (int fy = 0; fy < 3; fy++)
#pragma unroll
                    for (int fx = 0; fx < 3; fx++)
                        wmma::mma_sync(acc[fy][fx], af[fy], bf[fx], acc[fy][fx]);
            }
            __syncthreads();
        }

        float* Cs = sm;
#pragma unroll
        for (int fy = 0; fy < 3; fy++)
#pragma unroll
            for (int fx = 0; fx < 3; fx++)
                wmma::store_matrix_sync(Cs + (wy * 48 + fy * 16) * 196 + wx * 48 + fx * 16,
                                        acc[fy][fx], 196, wmma::mem_row_major);
        __syncthreads();
#pragma unroll
        for (int it = 0; it < 18; it++) {
            int idx = tid + it * 256;
            int row = idx / 48, c4 = (idx % 48) << 2;
            int grow = i0 + row;
            int seq = grow / Ll, tt = grow - seq * Ll;
            if (tt >= lenp[seq]) continue;
            float4 v = *(float4*)(Cs + row * 196 + c4);
            *(float4*)(C + (size_t)grow * 768 + n0 + c4) = v;
        }
        __syncthreads();
    }
}

// ---------------- fused recurrent GEMM + gate: tile 96x96, 128 thr, 4 blk/SM -------
__global__ void __launch_bounds__(128, 4) gru_step96(
    int t,
    const float* __restrict__ Whh,
    const float* __restrict__ xw,
    const float* __restrict__ bias_i,
    const int* __restrict__ lenp,
    const int* __restrict__ perm,
    const int* __restrict__ cnt,
    const float* __restrict__ h_prev, float* __restrict__ h_out,
    float* __restrict__ his_last)
{
    extern __shared__ float sm[];
    __shared__ int perm_s[96];
    __shared__ int len_s[96];

    const int i0 = blockIdx.x * 96;
    if (i0 >= cnt[t]) return;

    const int n0 = blockIdx.y * 96;
    const int tid = threadIdx.x;
    const int warp = tid >> 5;
    const int wy = warp >> 1, wx = warp & 1;

    if (tid < 96) {
        int p = perm[i0 + tid];
        perm_s[tid] = p;
        len_s[tid] = lenp[p];
    }

    wmma::fragment<wmma::accumulator, 16, 16, 8, float> acc[3][3];
#pragma unroll
    for (int a = 0; a < 3; a++)
#pragma unroll
        for (int b = 0; b < 3; b++) wmma::fill_fragment(acc[a][b], 0.f);

    if (t > 0) {
        auto cp_chunk = [&](int k0, int st) {
            float* As = sm + st * GSTG;
            float* Bs = As + 96 * 36;
#pragma unroll
            for (int it = 0; it < 6; it++) {
                int idx = tid + it * 128;
                int r = idx >> 3, k4 = (idx & 7) << 2;
                cp16(As + r * 36 + k4, h_prev + (size_t)(i0 + r) * 256 + k0 + k4);
            }
#pragma unroll
            for (int it = 0; it < 6; it++) {
                int idx = tid + it * 128;
                int rr = idx >> 3, k4 = (idx & 7) << 2;
                cp16(Bs + rr * 36 + k4, Whh + (size_t)(n0 + rr) * 256 + k0 + k4);
            }
            cp_commit();
        };

        cp_chunk(0, 0);
        for (int s = 0; s < 8; s++) {
            if (s + 1 < 8) {
                cp_chunk((s + 1) * 32, (s + 1) & 1);
                asm volatile("cp.async.wait_group 1;\n" ::: "memory");
            } else {
                asm volatile("cp.async.wait_group 0;\n" ::: "memory");
            }
            __syncthreads();
            float* As = sm + (s & 1) * GSTG;
            float* Bs = As + 96 * 36;
#pragma unroll
            for (int kk = 0; kk < 32; kk += 8) {
                wmma::fragment<wmma::matrix_a, 16, 16, 8, wmma::precision::tf32, wmma::row_major> af[3];
                wmma::fragment<wmma::matrix_b, 16, 16, 8, wmma::precision::tf32, wmma::col_major> bf[3];
#pragma unroll
                for (int fy = 0; fy < 3; fy++)
                    wmma::load_matrix_sync(af[fy], As + (wy * 48 + fy * 16) * 36 + kk, 36);
#pragma unroll
                for (int fx = 0; fx < 3; fx++)
                    wmma::load_matrix_sync(bf[fx], Bs + (wx * 48 + fx * 16) * 36 + kk, 36);
#pragma unroll
                for (int fy = 0; fy < 3; fy++)
#pragma unroll
                    for (int fx = 0; fx < 3; fx++)
                        wmma::mma_sync(acc[fy][fx], af[fy], bf[fx], acc[fy][fx]);
            }
            __syncthreads();
        }
    }

    // ---- single-pass gate epilogue via Cs[96][100]
    float* Cs = sm;
    __syncthreads();
#pragma unroll
    for (int fy = 0; fy < 3; fy++)
#pragma unroll
        for (int fx = 0; fx < 3; fx++)
            wmma::store_matrix_sync(Cs + (wy * 48 + fy * 16) * 100 + wx * 48 + fx * 16,
                                    acc[fy][fx], 100, wmma::mem_row_major);
    __syncthreads();

#pragma unroll
    for (int it = 0; it < 6; it++) {
        int idx = tid + it * 128;
        int row = idx >> 3;
        int q = idx & 7;
        int gi = i0 + row;
        int orig = perm_s[row];
        int c = q * 12;
        int j = blockIdx.y * 32 + q * 4;

        float GH[12], XW[12], BI[12], BH[12];
        *(float4*)&GH[0] = *(float4*)(Cs + row * 100 + c);
        *(float4*)&GH[4] = *(float4*)(Cs + row * 100 + c + 4);
        *(float4*)&GH[8] = *(float4*)(Cs + row * 100 + c + 8);
        const float* xwrow = xw + ((size_t)orig * Ll + t) * 768 + n0 + c;
        *(float4*)&XW[0] = *(const float4*)(xwrow);
        *(float4*)&XW[4] = *(const float4*)(xwrow + 4);
        *(float4*)&XW[8] = *(const float4*)(xwrow + 8);
        *(float4*)&BI[0] = *(const float4*)(bias_i + n0 + c);
        *(float4*)&BI[4] = *(const float4*)(bias_i + n0 + c + 4);
        *(float4*)&BI[8] = *(const float4*)(bias_i + n0 + c + 8);
        *(float4*)&BH[0] = *(const float4*)(bias_i + 768 + n0 + c);
        *(float4*)&BH[4] = *(const float4*)(bias_i + 768 + n0 + c + 4);
        *(float4*)&BH[8] = *(const float4*)(bias_i + 768 + n0 + c + 8);

        float4 hp = make_float4(0.f, 0.f, 0.f, 0.f);
        if (t > 0) hp = *(const float4*)(h_prev + (size_t)gi * 256 + j);
        float hps[4] = {hp.x, hp.y, hp.z, hp.w};
        float hn[4];
#pragma unroll
        for (int u = 0; u < 4; u++) {
            float r = sigmoidf_(XW[3 * u] + BI[3 * u] + GH[3 * u] + BH[3 * u]);
            float z = sigmoidf_(XW[3 * u + 1] + BI[3 * u + 1] + GH[3 * u + 1] + BH[3 * u + 1]);
            float n = tanhf(XW[3 * u + 2] + BI[3 * u + 2] + r * (GH[3 * u + 2] + BH[3 * u + 2]));
            hn[u] = (1.f - z) * n + z * hps[u];
        }
        float4 hv = make_float4(hn[0], hn[1], hn[2], hn[3]);
        *(float4*)(h_out + (size_t)gi * 256 + j) = hv;
        if (len_s[row] == t + 1)
            *(float4*)(his_last + (size_t)orig * 256 + j) = hv;
    }
}

// ---------------- wide tf32 GEMM (intra xw): tile 64x192 ---------------------------
__global__ void __launch_bounds__(256, 2) gemm_tc_wide(
    int M, int K,
    const float* __restrict__ A, int lda,
    const float* __restrict__ W, int ldw,
    float* __restrict__ C, int ldc)
{
    __shared__ float smem[64 * 36 + 192 * 36];
    float* As = smem;
    float* Bs = smem + 64 * 36;
    float* Cs = smem;

    int i0 = blockIdx.x * 64, n0 = blockIdx.y * 192;
    int tid = threadIdx.x;
    int warp = tid >> 5, wy = warp >> 2, wx = warp & 3;

    wmma::fragment<wmma::accumulator, 16, 16, 8, float> acc[2][3];
#pragma unroll
    for (int a = 0; a < 2; a++)
#pragma unroll
        for (int b = 0; b < 3; b++) wmma::fill_fragment(acc[a][b], 0.f);

    float4 ra[2], rb[6];
    auto ldchunk = [&](int k0) {
#pragma unroll
        for (int it = 0; it < 2; it++) {
            int idx = tid + it * 256;
            int r = idx >> 3, k4 = (idx & 7) << 2;
            float4 v = make_float4(0.f, 0.f, 0.f, 0.f);
            if (i0 + r < M) v = *(const float4*)(A + (size_t)(i0 + r) * lda + k0 + k4);
            ra[it] = v;
        }
#pragma unroll
        for (int it = 0; it < 6; it++) {
            int idx = tid + it * 256;
            int c = idx >> 3, k4 = (idx & 7) << 2;
            rb[it] = *(const float4*)(W + (size_t)(n0 + c) * ldw + k0 + k4);
        }
    };
    auto stchunk = [&]() {
#pragma unroll
        for (int it = 0; it < 2; it++) {
            int idx = tid + it * 256;
            int r = idx >> 3, k4 = (idx & 7) << 2;
            *(float4*)(As + r * 36 + k4) = tf32_4(ra[it]);
        }
#pragma unroll
        for (int it = 0; it < 6; it++) {
            int idx = tid + it * 256;
            int c = idx >> 3, k4 = (idx & 7) << 2;
            *(float4*)(Bs + c * 36 + k4) = tf32_4(rb[it]);
        }
    };

    ldchunk(0); stchunk(); __syncthreads();
    for (int k0 = 0; k0 < K; k0 += 32) {
        bool more = (k0 + 32) < K;
        if (more) ldchunk(k0 + 32);
#pragma unroll
        for (int kk = 0; kk < 32; kk += 8) {
            wmma::fragment<wmma::matrix_a, 16, 16, 8, wmma::precision::tf32, wmma::row_major> af[2];
            wmma::fragment<wmma::matrix_b, 16, 16, 8, wmma::precision::tf32, wmma::col_major> bf[3];
#pragma unroll
            for (int fy = 0; fy < 2; fy++)
                wmma::load_matrix_sync(af[fy], As + (wy * 32 + fy * 16) * 36 + kk, 36);
#pragma unroll
            for (int fx = 0; fx < 3; fx++)
                wmma::load_matrix_sync(bf[fx], Bs + (wx * 48 + fx * 16) * 36 + kk, 36);
#pragma unroll
            for (int fy = 0; fy < 2; fy++)
#pragma unroll
                for (int fx = 0; fx < 3; fx++)
                    wmma::mma_sync(acc[fy][fx], af[fy], bf[fx], acc[fy][fx]);
        }
        __syncthreads();
        if (more) { stchunk(); __syncthreads(); }
    }

    for (int pass = 0; pass < 2; pass++) {
        __syncthreads();
        if (wy == pass) {
#pragma unroll
            for (int fy = 0; fy < 2; fy++)
#pragma unroll
                for (int fx = 0; fx < 3; fx++)
                    wmma::store_matrix_sync(Cs + (fy * 16) * 196 + wx * 48 + fx * 16,
                                            acc[fy][fx], 196, wmma::mem_row_major);
        }
        __syncthreads();
#pragma unroll
        for (int it = 0; it < 6; it++) {
            int idx = tid + it * 256;
            int row = idx / 48, c4 = (idx % 48) << 2;
            int gi = i0 + pass * 32 + row;
            if (gi >= M) continue;
            float4 v = *(float4*)(Cs + row * 196 + c4);
            *(float4*)(C + (size_t)gi * ldc + n0 + c4) = v;
        }
    }
}

// ---------------- tf32 GEMM (tile 128x64): C = A @ W^T + bias ----------------------
__global__ void __launch_bounds__(256, 2) gemm_tc(
    int M, int N, int K,
    const float* __restrict__ A, int lda,
    const float* __restrict__ W, int ldw,
    const float* __restrict__ bias,
    float* __restrict__ C, int ldc)
{
    __shared__ float smem[128 * 68];
    float* As = smem;
    float* Bs = smem + 128 * 40;

    int i0 = blockIdx.x * 128, n0 = blockIdx.y * 64;
    int tid = threadIdx.x;
    int warp = tid >> 5;
    int wy = warp >> 1, wx = warp & 1;

    wmma::fragment<wmma::accumulator, 16, 16, 8, float> acc[2][2];
#pragma unroll
    for (int a = 0; a < 2; a++)
#pragma unroll
        for (int b = 0; b < 2; b++) wmma::fill_fragment(acc[a][b], 0.f);

    float4 ra[4], rb[2];
    auto ldchunk = [&](int k0) {
#pragma unroll
        for (int it = 0; it < 4; it++) {
            int idx = tid + it * 256;
            int r = idx >> 3, k4 = (idx & 7) << 2;
            float4 v = make_float4(0.f, 0.f, 0.f, 0.f);
            int gi = i0 + r;
            if (gi < M) v = *(const float4*)(A + (size_t)gi * lda + k0 + k4);
            ra[it] = v;
        }
#pragma unroll
        for (int it = 0; it < 2; it++) {
            int idx = tid + it * 256;
            int n = idx >> 3, k4 = (idx & 7) << 2;
            rb[it] = *(const float4*)(W + (size_t)(n0 + n) * ldw + k0 + k4);
        }
    };
    auto stchunk = [&]() {
#pragma unroll
        for (int it = 0; it < 4; it++) {
            int idx = tid + it * 256;
            int r = idx >> 3, k4 = (idx & 7) << 2;
            *(float4*)(As + r * 40 + k4) = tf32_4(ra[it]);
        }
#pragma unroll
        for (int it = 0; it < 2; it++) {
            int idx = tid + it * 256;
            int n = idx >> 3, k4 = (idx & 7) << 2;
            *(float4*)(Bs + n * 40 + k4) = tf32_4(rb[it]);
        }
    };

    ldchunk(0); stchunk(); __syncthreads();
    for (int k0 = 0; k0 < K; k0 += 32) {
        bool more = (k0 + 32) < K;
        if (more) ldchunk(k0 + 32);
#pragma unroll
        for (int kk = 0; kk < 32; kk += 8) {
            wmma::fragment<wmma::matrix_a, 16, 16, 8, wmma::precision::tf32, wmma::row_major> af[2];
            wmma::fragment<wmma::matrix_b, 16, 16, 8, wmma::precision::tf32, wmma::col_major> bf[2];
#pragma unroll
            for (int fy = 0; fy < 2; fy++)
                wmma::load_matrix_sync(af[fy], As + (wy * 32 + fy * 16) * 40 + kk, 40);
#pragma unroll
            for (int fx = 0; fx < 2; fx++)
                wmma::load_matrix_sync(bf[fx], Bs + (wx * 32 + fx * 16) * 40 + kk, 40);
#pragma unroll
            for (int fy = 0; fy < 2; fy++)
#pragma unroll
                for (int fx = 0; fx < 2; fx++)
                    wmma::mma_sync(acc[fy][fx], af[fy], bf[fx], acc[fy][fx]);
        }
        __syncthreads();
        if (more) { stchunk(); __syncthreads(); }
    }

    float* Cs = smem;
#pragma unroll
    for (int fy = 0; fy < 2; fy++)
#pragma unroll
        for (int fx = 0; fx < 2; fx++)
            wmma::store_matrix_sync(Cs + (wy * 32 + fy * 16) * 68 + wx * 32 + fx * 16,
                                    acc[fy][fx], 68, wmma::mem_row_major);
    __syncthreads();
#pragma unroll
    for (int it = 0; it < 8; it++) {
        int idx = tid + it * 256;
        int r = idx >> 4, c4 = (idx & 15) << 2;
        int gi = i0 + r;
        if (gi >= M) continue;
        float4 v = *(float4*)(Cs + r * 68 + c4);
        if (bias) {
            v.x += bias[n0 + c4];     v.y += bias[n0 + c4 + 1];
            v.z += bias[n0 + c4 + 2]; v.w += bias[n0 + c4 + 3];
        }
        *(float4*)(C + (size_t)gi * ldc + n0 + c4) = v;
    }
}

// ---------------- fused intra GRU: coalesced transposed weights --------------------
__global__ void __launch_bounds__(768) intra_gru(
    const float* __restrict__ xw_intra,
    const float* __restrict__ w_hhT,          // [256][768]
    const float* __restrict__ b_ih, const float* __restrict__ b_hh,
    float* __restrict__ intra_h)
{
    int b = blockIdx.x;
    int tid = threadIdx.x;
    __shared__ float h_sh[256];
    __shared__ float gh_sh[768];
    if (tid < 256) h_sh[tid] = 0.f;
    __syncthreads();
    for (int t = 0; t < Ss; t++) {
        float a0 = 0.f, a1 = 0.f, a2 = 0.f, a3 = 0.f;
#pragma unroll 16
        for (int k = 0; k < 256; k += 4) {
            a0 += w_hhT[(size_t)(k + 0) * 768 + tid] * h_sh[k + 0];
            a1 += w_hhT[(size_t)(k + 1) * 768 + tid] * h_sh[k + 1];
            a2 += w_hhT[(size_t)(k + 2) * 768 + tid] * h_sh[k + 2];
            a3 += w_hhT[(size_t)(k + 3) * 768 + tid] * h_sh[k + 3];
        }
        gh_sh[tid] = (a0 + a1) + (a2 + a3);
        __syncthreads();
        if (tid < 256) {
            const float* xwrow = xw_intra + ((size_t)b * Ss + t) * 768;
            float r = sigmoidf_(xwrow[3 * tid] + b_ih[tid] + gh_sh[tid] + b_hh[tid]);
            float z = sigmoidf_(xwrow[3 * tid + 1] + b_ih[256 + tid] + gh_sh[256 + tid] + b_hh[256 + tid]);
            float n = tanhf(xwrow[3 * tid + 2] + b_ih[512 + tid] + r * (gh_sh[512 + tid] + b_hh[512 + tid]));
            float hn = (1.f - z) * n + z * h_sh[tid];
            h_sh[tid] = hn;
            intra_h[((size_t)b * Ss + t) * 256 + tid] = hn;
        }
        __syncthreads();
    }
}

// ---------------- build_feat ----------------
__global__ void build_feat(const float* __restrict__ intra_x, const float* __restrict__ wr,
                           const float* __restrict__ vv, const float* __restrict__ vh,
                           const float* __restrict__ intra_h, float* __restrict__ feat) {
    int idx = blockIdx.x * blockDim.x + threadIdx.x;
    if (idx >= BS * 640) return;
    float e0 = expf(wr[0]), e1 = expf(wr[1]);
    float w0 = e0 / (e0 + e1), w1 = 1.f - w0;
    int i = idx / 640, c = idx % 640;
    float v;
    if (c < 256) v = w0 * vv[i * 256 + c] + w1 * vh[i * 256 + c];
    else if (c < 512) v = intra_h[i * 256 + (c - 256)];
    else if (c < 639) v = intra_x[i * 128 + (c - 512)];
    else v = 0.f;
    feat[idx] = v;
}

// ---------------- attention cores ----------------
__global__ void __launch_bounds__(256) inter_attn2(
    const float* __restrict__ qi, const float* __restrict__ kvi, float* __restrict__ oi)
{
    int warp = threadIdx.x >> 5, lane = threadIdx.x & 31;
    int item = blockIdx.x * 8 + warp;
    int row = item >> 1, head = item & 1;
    int off = head * 128 + lane * 4;

    float4 q = *(const float4*)(qi + (size_t)row * 256 + off);
    float p[6];
#pragma unroll
    for (int r = 0; r < 6; r++) {
        float4 k4 = *(const float4*)(kvi + (size_t)(row * 6 + r) * 512 + off);
        float d = q.x * k4.x + q.y * k4.y + q.z * k4.z + q.w * k4.w;
#pragma unroll
        for (int o = 16; o; o >>= 1) d += __shfl_xor_sync(0xffffffffu, d, o);
        p[r] = d * 0.08838834764831843f;
    }
    float mx = p[0];
#pragma unroll
    for (int r = 1; r < 6; r++) mx = fmaxf(mx, p[r]);
    float sum = 0.f;
#pragma unroll
    for (int r = 0; r < 6; r++) { p[r] = expf(p[r] - mx); sum += p[r]; }
    float inv = 1.f / sum;
    float4 acc = make_float4(0.f, 0.f, 0.f, 0.f);
#pragma unroll
    for (int r = 0; r < 6; r++) {
        float4 v4 = *(const float4*)(kvi + (size_t)(row * 6 + r) * 512 + 256 + off);
        float w = p[r] * inv;
        acc.x += w * v4.x; acc.y += w * v4.y; acc.z += w * v4.z; acc.w += w * v4.w;
    }
    *(float4*)(oi + (size_t)row * 256 + off) = acc;
}

// intra: block per (head, batch); q/k from fused qkh [row][512] (q at 0, k at 256).
__global__ void __launch_bounds__(256) intra_attn2(
    const float* __restrict__ qkh,
    const float* __restrict__ vhp, float* __restrict__ oh)
{
    extern __shared__ float sm[];
    float* Qs = sm + IA_QS;
    float* Ks = sm + IA_KS;
    float* Vs = sm + IA_VS;
    float* Ps = sm + IA_PS;

    int head = blockIdx.x, b = blockIdx.y;
    int tid = threadIdx.x;

    for (int idx = tid; idx < 64 * 32; idx += 256) {
        int row = idx >> 5, c4 = (idx & 31) << 2;
        size_t gq = (size_t)(b * 64 + row) * 512 + head * 128 + c4;
        size_t gv = (size_t)(b * 64 + row) * 256 + head * 128 + c4;
        *(float4*)(Qs + row * 132 + c4) = *(const float4*)(qkh + gq);
        *(float4*)(Ks + row * 132 + c4) = *(const float4*)(qkh + gq + 256);
        *(float4*)(Vs + row * 132 + c4) = *(const float4*)(vhp + gv);
    }
    __syncthreads();

    for (int idx = tid; idx < 64 * 64; idx += 256) {
        int tq = idx >> 6, tk = idx & 63;
        if (tk > tq) continue;
        const float4* qp = (const float4*)(Qs + tq * 132);
        const float4* kp = (const float4*)(Ks + tk * 132);
        float acc = 0.f;
#pragma unroll
        for (int k = 0; k < 32; k++) {
            float4 a = qp[k], c = kp[k];
            acc += a.x * c.x + a.y * c.y + a.z * c.z + a.w * c.w;
        }
        Ps[tq * 65 + tk] = acc * 0.08838834764831843f;
    }
    __syncthreads();

    if (tid < 64) {
        int tq = tid;
        float mx = -1e30f;
        for (int k = 0; k <= tq; k++) mx = fmaxf(mx, Ps[tq * 65 + k]);
        float sum = 0.f;
        for (int k = 0; k <= tq; k++) { float e = expf(Ps[tq * 65 + k] - mx); Ps[tq * 65 + k] = e; sum += e; }
        float inv = 1.f / sum;
        for (int k = 0; k <= tq; k++) Ps[tq * 65 + k] *= inv;
    }
    __syncthreads();

    for (int idx = tid; idx < 64 * 32; idx += 256) {
        int tq = idx >> 5, d4 = (idx & 31) << 2;
        float4 acc = make_float4(0.f, 0.f, 0.f, 0.f);
        for (int k = 0; k <= tq; k++) {
            float w = Ps[tq * 65 + k];
            float4 v = *(float4*)(Vs + k * 132 + d4);
            acc.x += w * v.x; acc.y += w * v.y; acc.z += w * v.z; acc.w += w * v.w;
        }
        *(float4*)(oh + (size_t)(b * 64 + tq) * 256 + head * 128 + d4) = acc;
    }
}

// ---------------- launch ----------------
extern "C" void kernel_launch(void* const* d_in, const int* in_sizes, int n_in,
                              void* d_out, int out_size) {
    const float* intra_x   = (const float*)d_in[0];
    const float* inter_his = (const float*)d_in[1];
    const float* inter_r   = (const float*)d_in[2];
    const int*   inter_len = (const int*)d_in[4];
    const float* w_ih = (const float*)d_in[5];
    const float* w_hh = (const float*)d_in[6];
    const float* b_ih = (const float*)d_in[7];
    const float* b_hh = (const float*)d_in[8];
    const float* iq_w = (const float*)d_in[9];
    const float* iq_b = (const float*)d_in[10];
    const float* ik_w = (const float*)d_in[11];
    const float* ik_b = (const float*)d_in[12];
    const float* iv_w = (const float*)d_in[13];
    const float* iv_b = (const float*)d_in[14];
    const float* io_w = (const float*)d_in[15];
    const float* io_b = (const float*)d_in[16];
    const float* aq_w = (const float*)d_in[17];
    const float* aq_b = (const float*)d_in[18];
    const float* ak_w = (const float*)d_in[19];
    const float* ak_b = (const float*)d_in[20];
    const float* av_w = (const float*)d_in[21];
    const float* av_b = (const float*)d_in[22];
    const float* ao_w = (const float*)d_in[23];
    const float* ao_b = (const float*)d_in[24];
    const float* wr   = (const float*)d_in[25];
    const float* ln_w = (const float*)d_in[26];
    const float* ln_b = (const float*)d_in[27];
    float* out = (float*)d_out;

    float *p_Whh_i, *p_WhhT, *p_Wih_i, *p_bias_i, *p_xw, *p_xw_intra, *p_hA, *p_hB, *p_his, *p_ih;
    float *p_Mrv, *p_mpv, *p_hp, *p_qi, *p_kvi, *p_oi, *p_vv, *p_qkh, *p_vhp;
    float *p_oh, *p_vh, *p_feat, *p_Wq, *p_Wkv, *p_bias_kv, *p_Waqk, *p_bias_aqk, *p_Wav, *p_Wln;
    int *p_perm, *p_cnt;
    cudaGetSymbolAddress((void**)&p_Whh_i, g_Whh_i);
    cudaGetSymbolAddress((void**)&p_WhhT, g_WhhT);
    cudaGetSymbolAddress((void**)&p_Wih_i, g_Wih_i);
    cudaGetSymbolAddress((void**)&p_bias_i, g_bias_i);
    cudaGetSymbolAddress((void**)&p_xw, g_xw_inter);
    cudaGetSymbolAddress((void**)&p_xw_intra, g_xw_intra);
    cudaGetSymbolAddress((void**)&p_hA, g_hA);
    cudaGetSymbolAddress((void**)&p_hB, g_hB);
    cudaGetSymbolAddress((void**)&p_his, g_his_last);
    cudaGetSymbolAddress((void**)&p_ih, g_intra_h);
    cudaGetSymbolAddress((void**)&p_Mrv, g_Mrv);
    cudaGetSymbolAddress((void**)&p_mpv, g_mpv);
    cudaGetSymbolAddress((void**)&p_hp, g_hp);
    cudaGetSymbolAddress((void**)&p_qi, g_qi);
    cudaGetSymbolAddress((void**)&p_kvi, g_kvi);
    cudaGetSymbolAddress((void**)&p_oi, g_oi);
    cudaGetSymbolAddress((void**)&p_vv, g_vv);
    cudaGetSymbolAddress((void**)&p_qkh, g_qkh);
    cudaGetSymbolAddress((void**)&p_vhp, g_vhp);
    cudaGetSymbolAddress((void**)&p_oh, g_oh);
    cudaGetSymbolAddress((void**)&p_vh, g_vh);
    cudaGetSymbolAddress((void**)&p_feat, g_feat);
    cudaGetSymbolAddress((void**)&p_Wq, g_Wq);
    cudaGetSymbolAddress((void**)&p_Wkv, g_Wkv);
    cudaGetSymbolAddress((void**)&p_bias_kv, g_bias_kv);
    cudaGetSymbolAddress((void**)&p_Waqk, g_Waqk);
    cudaGetSymbolAddress((void**)&p_bias_aqk, g_bias_aqk);
    cudaGetSymbolAddress((void**)&p_Wav, g_Wav);
    cudaGetSymbolAddress((void**)&p_Wln, g_Wln);
    cudaGetSymbolAddress((void**)&p_perm, g_perm);
    cudaGetSymbolAddress((void**)&p_cnt, g_cnt);

    static cudaStream_t s1 = nullptr;
    static cudaEvent_t ev_fork = nullptr, ev_join = nullptr;
    static bool attr_set = false;
    if (!attr_set) {
        cudaFuncSetAttribute(gemm96_cp, cudaFuncAttributeMaxDynamicSharedMemorySize, SMEMF * 4);
        cudaFuncSetAttribute(gru_step96, cudaFuncAttributeMaxDynamicSharedMemorySize, GSMEMF * 4);
        cudaFuncSetAttribute(intra_attn2, cudaFuncAttributeMaxDynamicSharedMemorySize, IA_FLOATS * 4);
        cudaStreamCreateWithFlags(&s1, cudaStreamNonBlocking);
        cudaEventCreateWithFlags(&ev_fork, cudaEventDisableTiming);
        cudaEventCreateWithFlags(&ev_join, cudaEventDisableTiming);
        attr_set = true;
    }

    // ---- prep (main stream)
    len_sort_all<<<1, 1024>>>(inter_len);
    prep_whh_i<<<(768 * 256 + 255) / 256, 256>>>(w_hh, p_Whh_i);
    prep_bias_i<<<3, 256>>>(b_ih, b_hh, p_bias_i);
    prep_wih_i<<<(768 * 128 + 255) / 256, 256>>>(w_ih, p_Wih_i);

    // ---- fork: intra path + weight padding run concurrently with the inter chain
    cudaEventRecord(ev_fork, 0);
    cudaStreamWaitEvent(s1, ev_fork, 0);
    prep_whhT<<<(256 * 768 + 255) / 256, 256, 0, s1>>>(w_hh, p_WhhT);
    gemm_tc_wide<<<dim3(16, 4), 256, 0, s1>>>(BS, 128, intra_x, 128, p_Wih_i, 128, p_xw_intra, 768);
    intra_gru<<<Bb, 768, 0, s1>>>(p_xw_intra, p_WhhT, b_ih, b_hh, p_ih);
    pad_all<<<(599040 + 255) / 256, 256, 0, s1>>>(iq_w, ik_w, iv_w, aq_w, ak_w, av_w, ln_w,
                                                  ik_b, iv_b, aq_b, ak_b);
    cudaEventRecord(ev_join, s1);

    // ---- main stream: hoisted inter input projection + GRU chain
    gemm96_cp<<<NROWS_XW / 96, 256, SMEMF * 4>>>(inter_his, p_Wih_i, p_xw, inter_len);
    for (int t = 0; t < Ll; t++) {
        float* h_out  = (t & 1) ? p_hB : p_hA;
        float* h_prev = (t & 1) ? p_hA : p_hB;
        gru_step96<<<dim3(NSEQ / 96, 8), 128, GSMEMF * 4>>>(t, p_Whh_i, p_xw, p_bias_i,
                                                            inter_len, p_perm, p_cnt,
                                                            h_prev, h_out, p_his);
    }

    // ---- join: build_all needs his_last (chain) + intra_h (s1); GEMMs need pad_all
    cudaStreamWaitEvent(0, ev_join, 0);
    build_all<<<(3015680 + 255) / 256, 256>>>(inter_r, intra_x);

    // inter MHA (K/V fused into one N=512 GEMM)
    gemm_tc<<<dim3(8, 4), 256>>>(BS, 256, 384, p_mpv, 384, p_Wq, 384, iq_b, p_qi, 256);
    gemm_tc<<<dim3(48, 8), 256>>>(NSEQ, 512, 384, p_Mrv, 384, p_Wkv, 384, p_bias_kv, p_kvi, 512);
    inter_attn2<<<256, 256>>>(p_qi, p_kvi, p_oi);
    gemm_tc<<<dim3(8, 4), 256>>>(BS, 256, 256, p_oi, 256, io_w, 256, io_b, p_vv, 256);

    // intra MHA (q+k fused into one N=512 GEMM)
    gemm_tc<<<dim3(8, 8), 256>>>(BS, 512, 128, intra_x, 128, p_Waqk, 128, p_bias_aqk, p_qkh, 512);
    gemm_tc<<<dim3(8, 4), 256>>>(BS, 256, 288, p_hp, 288, p_Wav, 288, av_b, p_vhp, 256);
    intra_attn2<<<dim3(2, 16), 256, IA_FLOATS * 4>>>(p_qkh, p_vhp, p_oh);
    gemm_tc<<<dim3(8, 4), 256>>>(BS, 256, 256, p_oh, 256, ao_w, 256, ao_b, p_vh, 256);

    // combine + final projection
    build_feat<<<(BS * 640 + 255) / 256, 256>>>(intra_x, wr, p_vv, p_vh, p_ih, p_feat);
    gemm_tc<<<dim3(8, 4), 256>>>(BS, 256, 640, p_feat, 640, p_Wln, 640, ln_b, out, 256);
}

// round 17
// speedup vs baseline: 2.4517x; 1.0437x over previous
#include <cuda_runtime.h>
#include <mma.h>
#include <math.h>
using namespace nvcuda;

// Problem dims
#define Bb 16
#define Ss 64
#define Rr 6
#define Ll 24
#define Dd 128
#define Hh 256
#define BS 1024      // B*S
#define NSEQ 6144    // B*S*R
#define NROWS_XW (NSEQ * Ll)   // 147456

// smem stage geometry for gemm96_cp (floats)
#define ASZ96 (96 * 36)        // 3456
#define BSZ   (192 * 36)       // 6912
#define STAGE (ASZ96 + BSZ)    // 10368
#define SMEMF (2 * STAGE)      // 20736 floats = 82944 B

// gru_step96 small-tile stage geometry (floats)
#define GSTG (96 * 36 + 96 * 36)     // 6912 per stage
#define GSMEMF (2 * GSTG)            // 13824 floats = 55296 B

// intra_attn smem layout (floats)
#define IA_QS 0
#define IA_KS 8448
#define IA_VS 16896
#define IA_PS 25344
#define IA_FLOATS 29504

// ---------------- scratch (device globals; no allocations allowed) ----------------
__device__ float g_Whh_i[768 * 256];
__device__ float g_WhhT[256 * 768];
__device__ float g_Wih_i[768 * 128];
__device__ float g_bias_i[2 * 768];
__device__ float g_xw_inter[(size_t)NROWS_XW * 768];
__device__ float g_xw_intra[BS * 768];
__device__ float g_hA[NSEQ * Hh];
__device__ float g_hB[NSEQ * Hh];
__device__ float g_his_last[NSEQ * Hh];
__device__ float g_intra_h[BS * Hh];
__device__ float g_Mrv[NSEQ * 384];
__device__ float g_mpv[BS * 384];
__device__ float g_hp[BS * 288];
__device__ float g_qi[BS * Hh];
__device__ float g_kvi[NSEQ * 512];
__device__ float g_oi[BS * Hh];
__device__ float g_vv[BS * Hh];
__device__ float g_qkh[BS * 512];
__device__ float g_vhp[BS * Hh];
__device__ float g_oh[BS * Hh];
__device__ float g_vh[BS * Hh];
__device__ float g_feat[BS * 640];
__device__ float g_Wq[256 * 384];
__device__ float g_Wkv[512 * 384];
__device__ float g_bias_kv[512];
__device__ float g_Waqk[512 * 128];
__device__ float g_bias_aqk[512];
__device__ float g_Wav[256 * 288];
__device__ float g_Wln[256 * 640];
// length sort
__device__ int g_cnt[Ll];
__device__ int g_perm[NSEQ];

__device__ __forceinline__ float sigmoidf_(float x) {
    return __fdividef(1.f, 1.f + __expf(-x));
}
__device__ __forceinline__ float4 tf32_4(float4 v) {
    v.x = wmma::__float_to_tf32(v.x);
    v.y = wmma::__float_to_tf32(v.y);
    v.z = wmma::__float_to_tf32(v.z);
    v.w = wmma::__float_to_tf32(v.w);
    return v;
}
__device__ __forceinline__ void cp16(float* sdst, const float* gsrc) {
    unsigned saddr = (unsigned)__cvta_generic_to_shared(sdst);
    asm volatile("cp.async.cg.shared.global [%0], [%1], 16;\n" :: "r"(saddr), "l"(gsrc));
}
__device__ __forceinline__ void cp_commit() {
    asm volatile("cp.async.commit_group;\n" ::: "memory");
}

// ---------------- fused length sort (one block) ----------------
__global__ void __launch_bounds__(1024) len_sort_all(const int* __restrict__ lenp) {
    __shared__ int bins_s[32], start_s[32], cur_s[32];
    int tid = threadIdx.x;
    if (tid < 32) { bins_s[tid] = 0; cur_s[tid] = 0; }
    __syncthreads();
    for (int i = tid; i < NSEQ; i += 1024) atomicAdd(&bins_s[lenp[i]], 1);
    __syncthreads();
    if (tid == 0) {
        int s = 0;
        for (int l = Ll; l >= 1; l--) { start_s[l] = s; s += bins_s[l]; }
        for (int t = 0; t < Ll; t++) {
            int c = 0;
            for (int l = t + 1; l <= Ll; l++) c += bins_s[l];
            g_cnt[t] = c;
        }
    }
    __syncthreads();
    for (int i = tid; i < NSEQ; i += 1024) {
        int l = lenp[i];
        int pos = start_s[l] + atomicAdd(&cur_s[l], 1);
        g_perm[pos] = i;
    }
}

// ---------------- weight interleaving ----------------
__global__ void prep_whh_i(const float* __restrict__ w_hh, float* __restrict__ dst) {
    int idx = blockIdx.x * blockDim.x + threadIdx.x;
    if (idx >= 768 * 256) return;
    int row = idx >> 8, k = idx & 255;
    int j = row / 3, g = row % 3;
    dst[idx] = w_hh[(g * 256 + j) * 256 + k];
}
__global__ void prep_whhT(const float* __restrict__ w_hh, float* __restrict__ dst) {
    int idx = blockIdx.x * blockDim.x + threadIdx.x;
    if (idx >= 256 * 768) return;
    int k = idx / 768, row = idx % 768;
    dst[idx] = w_hh[row * 256 + k];
}
__global__ void prep_wih_i(const float* __restrict__ w_ih, float* __restrict__ dst) {
    int idx = blockIdx.x * blockDim.x + threadIdx.x;
    if (idx >= 768 * 128) return;
    int row = idx >> 7, k = idx & 127;
    int j = row / 3, g = row % 3;
    dst[idx] = w_ih[(g * 256 + j) * 128 + k];
}
__global__ void prep_bias_i(const float* __restrict__ b_ih, const float* __restrict__ b_hh,
                            float* __restrict__ dst) {
    int idx = blockIdx.x * blockDim.x + threadIdx.x;
    if (idx >= 768) return;
    int j = idx / 3, g = idx % 3;
    dst[idx] = b_ih[g * 256 + j];
    dst[768 + idx] = b_hh[g * 256 + j];
}

// ---------------- merged weight padding ----------------
__global__ void pad_all(const float* __restrict__ iq_w, const float* __restrict__ ik_w,
                        const float* __restrict__ iv_w, const float* __restrict__ aq_w,
                        const float* __restrict__ ak_w, const float* __restrict__ av_w,
                        const float* __restrict__ ln_w, const float* __restrict__ ik_b,
                        const float* __restrict__ iv_b, const float* __restrict__ aq_b,
                        const float* __restrict__ ak_b) {
    int idx = blockIdx.x * blockDim.x + threadIdx.x;
    if (idx < 98304) { int n = idx / 384, k = idx % 384; g_Wq[idx] = (k < 383) ? iq_w[n * 383 + k] : 0.f; return; }
    idx -= 98304;
    if (idx < 98304) { int n = idx / 384, k = idx % 384; g_Wkv[idx] = (k < 383) ? ik_w[n * 383 + k] : 0.f; return; }
    idx -= 98304;
    if (idx < 98304) { g_Wkv[98304 + idx] = iv_w[idx]; return; }
    idx -= 98304;
    if (idx < 32768) { int n = idx / 128, k = idx % 128; g_Waqk[idx] = (k < 127) ? aq_w[n * 127 + k] : 0.f; return; }
    idx -= 32768;
    if (idx < 32768) { int n = idx / 128, k = idx % 128; g_Waqk[32768 + idx] = (k < 127) ? ak_w[n * 127 + k] : 0.f; return; }
    idx -= 32768;
    if (idx < 73728) { int n = idx / 288, k = idx % 288; g_Wav[idx] = (k < 257) ? av_w[n * 257 + k] : 0.f; return; }
    idx -= 73728;
    if (idx < 163840) { int n = idx / 640, k = idx % 640; g_Wln[idx] = (k < 639) ? ln_w[n * 639 + k] : 0.f; return; }
    idx -= 163840;
    if (idx < 512) { g_bias_kv[idx] = (idx < 256) ? ik_b[idx] : iv_b[idx - 256]; return; }
    idx -= 512;
    if (idx < 512) g_bias_aqk[idx] = (idx < 256) ? aq_b[idx] : ak_b[idx - 256];
}

// ---------------- split builders ----------------
// intra-side: mpv + hp (depend only on intra_h / intra_x) — runs on s1
__global__ void build_intra(const float* __restrict__ intra_x) {
    int idx = blockIdx.x * blockDim.x + threadIdx.x;
    if (idx < BS * 384) {
        int i = idx / 384, c = idx % 384;
        float v;
        if (c < 256) v = g_intra_h[i * 256 + c];
        else if (c < 383) v = intra_x[i * 128 + (c - 256)];
        else v = 0.f;
        g_mpv[idx] = v;
        return;
    }
    idx -= BS * 384;
    if (idx < BS * 257) {
        int i = idx / 257, c = idx % 257;
        g_hp[i * 288 + c] = (c < 256) ? g_intra_h[i * 256 + c] : intra_x[i * 128 + 127];
    }
}
// inter-side: Mrv (needs his_last) — runs on main after the chain
__global__ void build_mrv(const float* __restrict__ inter_r) {
    int idx = blockIdx.x * blockDim.x + threadIdx.x;
    if (idx >= NSEQ * 384) return;
    int i = idx / 384, c = idx % 384;
    g_Mrv[idx] = (c < 256) ? g_his_last[i * 256 + c] : inter_r[i * 128 + (c - 256)];
}

// ---------------- xw projection: tile 96x768 (n0 loop, A L2-resident) --------------
__global__ void __launch_bounds__(256, 2) gemm96_cp(
    const float* __restrict__ A,
    const float* __restrict__ W,
    float* __restrict__ C,
    const int* __restrict__ lenp)
{
    extern __shared__ float sm[];
    const int i0 = blockIdx.x * 96;
    const int tid = threadIdx.x;
    const int warp = tid >> 5;
    const int wy = warp >> 2, wx = warp & 3;

    for (int n0 = 0; n0 < 768; n0 += 192) {
        wmma::fragment<wmma::accumulator, 16, 16, 8, float> acc[3][3];
#pragma unroll
        for (int a = 0; a < 3; a++)
#pragma unroll
            for (int b = 0; b < 3; b++) wmma::fill_fragment(acc[a][b], 0.f);

        auto cp_chunk = [&](int k0, int st) {
            float* As = sm + st * STAGE;
            float* Bs = As + ASZ96;
#pragma unroll
            for (int it = 0; it < 3; it++) {
                int idx = tid + it * 256;
                int r = idx >> 3, k4 = (idx & 7) << 2;
                cp16(As + r * 36 + k4, A + (size_t)(i0 + r) * 128 + k0 + k4);
            }
#pragma unroll
            for (int it = 0; it < 6; it++) {
                int idx = tid + it * 256;
                int rr = idx >> 3, k4 = (idx & 7) << 2;
                cp16(Bs + rr * 36 + k4, W + (size_t)(n0 + rr) * 128 + k0 + k4);
            }
            cp_commit();
        };

        cp_chunk(0, 0);
        for (int s = 0; s < 4; s++) {
            if (s + 1 < 4) {
                cp_chunk((s + 1) * 32, (s + 1) & 1);
                asm volatile("cp.async.wait_group 1;\n" ::: "memory");
            } else {
                asm volatile("cp.async.wait_group 0;\n" ::: "memory");
            }
            __syncthreads();
            float* As = sm + (s & 1) * STAGE;
            float* Bs = As + ASZ96;
#pragma unroll
            for (int kk = 0; kk < 32; kk += 8) {
                wmma::fragment<wmma::matrix_a, 16, 16, 8, wmma::precision::tf32, wmma::row_major> af[3];
                wmma::fragment<wmma::matrix_b, 16, 16, 8, wmma::precision::tf32, wmma::col_major> bf[3];
#pragma unroll
                for (int fy = 0; fy < 3; fy++)
                    wmma::load_matrix_sync(af[fy], As + (wy * 48 + fy * 16) * 36 + kk, 36);
#pragma unroll
                for (int fx = 0; fx < 3; fx++)
                    wmma::load_matrix_sync(bf[fx], Bs + (wx * 48 + fx * 16) * 36 + kk, 36);
#pragma unroll
                for (int fy = 0; fy < 3; fy++)
#pragma unroll
                    for (int fx = 0; fx < 3; fx++)
                        wmma::mma_sync(acc[fy][fx], af[fy], bf[fx], acc[fy][fx]);
            }
            __syncthreads();
        }

        float* Cs = sm;
#pragma unroll
        for (int fy = 0; fy < 3; fy++)
#pragma unroll
            for (int fx = 0; fx < 3; fx++)
                wmma::store_matrix_sync(Cs + (wy * 48 + fy * 16) * 196 + wx * 48 + fx * 16,
                                        acc[fy][fx], 196, wmma::mem_row_major);
        __syncthreads();
#pragma unroll
        for (int it = 0; it < 18; it++) {
            int idx = tid + it * 256;
            int row = idx / 48, c4 = (idx % 48) << 2;
            int grow = i0 + row;
            int seq = grow / Ll, tt = grow - seq * Ll;
            if (tt >= lenp[seq]) continue;
            float4 v = *(float4*)(Cs + row * 196 + c4);
            *(float4*)(C + (size_t)grow * 768 + n0 + c4) = v;
        }
        __syncthreads();
    }
}

// ---------------- fused recurrent GEMM + gate: tile 96x96, 128 thr, 4 blk/SM -------
__global__ void __launch_bounds__(128, 4) gru_step96(
    int t,
    const float* __restrict__ Whh,
    const float* __restrict__ xw,
    const float* __restrict__ bias_i,
    const int* __restrict__ lenp,
    const int* __restrict__ perm,
    const int* __restrict__ cnt,
    const float* __restrict__ h_prev, float* __restrict__ h_out,
    float* __restrict__ his_last)
{
    extern __shared__ float sm[];
    __shared__ int perm_s[96];
    __shared__ int len_s[96];

    const int i0 = blockIdx.x * 96;
    if (i0 >= cnt[t]) return;

    const int n0 = blockIdx.y * 96;
    const int tid = threadIdx.x;
    const int warp = tid >> 5;
    const int wy = warp >> 1, wx = warp & 1;

    if (tid < 96) {
        int p = perm[i0 + tid];
        perm_s[tid] = p;
        len_s[tid] = lenp[p];
    }

    wmma::fragment<wmma::accumulator, 16, 16, 8, float> acc[3][3];
#pragma unroll
    for (int a = 0; a < 3; a++)
#pragma unroll
        for (int b = 0; b < 3; b++) wmma::fill_fragment(acc[a][b], 0.f);

    if (t > 0) {
        auto cp_chunk = [&](int k0, int st) {
            float* As = sm + st * GSTG;
            float* Bs = As + 96 * 36;
#pragma unroll
            for (int it = 0; it < 6; it++) {
                int idx = tid + it * 128;
                int r = idx >> 3, k4 = (idx & 7) << 2;
                cp16(As + r * 36 + k4, h_prev + (size_t)(i0 + r) * 256 + k0 + k4);
            }
#pragma unroll
            for (int it = 0; it < 6; it++) {
                int idx = tid + it * 128;
                int rr = idx >> 3, k4 = (idx & 7) << 2;
                cp16(Bs + rr * 36 + k4, Whh + (size_t)(n0 + rr) * 256 + k0 + k4);
            }
            cp_commit();
        };

        cp_chunk(0, 0);
        for (int s = 0; s < 8; s++) {
            if (s + 1 < 8) {
                cp_chunk((s + 1) * 32, (s + 1) & 1);
                asm volatile("cp.async.wait_group 1;\n" ::: "memory");
            } else {
                asm volatile("cp.async.wait_group 0;\n" ::: "memory");
            }
            __syncthreads();
            float* As = sm + (s & 1) * GSTG;
            float* Bs = As + 96 * 36;
#pragma unroll
            for (int kk = 0; kk < 32; kk += 8) {
                wmma::fragment<wmma::matrix_a, 16, 16, 8, wmma::precision::tf32, wmma::row_major> af[3];
                wmma::fragment<wmma::matrix_b, 16, 16, 8, wmma::precision::tf32, wmma::col_major> bf[3];
#pragma unroll
                for (int fy = 0; fy < 3; fy++)
                    wmma::load_matrix_sync(af[fy], As + (wy * 48 + fy * 16) * 36 + kk, 36);
#pragma unroll
                for (int fx = 0; fx < 3; fx++)
                    wmma::load_matrix_sync(bf[fx], Bs + (wx * 48 + fx * 16) * 36 + kk, 36);
#pragma unroll
                for (int fy = 0; fy < 3; fy++)
#pragma unroll
                    for (int fx = 0; fx < 3; fx++)
                        wmma::mma_sync(acc[fy][fx], af[fy], bf[fx], acc[fy][fx]);
            }
            __syncthreads();
        }
    }

    // ---- single-pass gate epilogue via Cs[96][100]
    float* Cs = sm;
    __syncthreads();
#pragma unroll
    for (int fy = 0; fy < 3; fy++)
#pragma unroll
        for (int fx = 0; fx < 3; fx++)
            wmma::store_matrix_sync(Cs + (wy * 48 + fy * 16) * 100 + wx * 48 + fx * 16,
                                    acc[fy][fx], 100, wmma::mem_row_major);
    __syncthreads();

#pragma unroll
    for (int it = 0; it < 6; it++) {
        int idx = tid + it * 128;
        int row = idx >> 3;
        int q = idx & 7;
        int gi = i0 + row;
        int orig = perm_s[row];
        int c = q * 12;
        int j = blockIdx.y * 32 + q * 4;

        float GH[12], XW[12], BI[12], BH[12];
        *(float4*)&GH[0] = *(float4*)(Cs + row * 100 + c);
        *(float4*)&GH[4] = *(float4*)(Cs + row * 100 + c + 4);
        *(float4*)&GH[8] = *(float4*)(Cs + row * 100 + c + 8);
        const float* xwrow = xw + ((size_t)orig * Ll + t) * 768 + n0 + c;
        *(float4*)&XW[0] = *(const float4*)(xwrow);
        *(float4*)&XW[4] = *(const float4*)(xwrow + 4);
        *(float4*)&XW[8] = *(const float4*)(xwrow + 8);
        *(float4*)&BI[0] = *(const float4*)(bias_i + n0 + c);
        *(float4*)&BI[4] = *(const float4*)(bias_i + n0 + c + 4);
        *(float4*)&BI[8] = *(const float4*)(bias_i + n0 + c + 8);
        *(float4*)&BH[0] = *(const float4*)(bias_i + 768 + n0 + c);
        *(float4*)&BH[4] = *(const float4*)(bias_i + 768 + n0 + c + 4);
        *(float4*)&BH[8] = *(const float4*)(bias_i + 768 + n0 + c + 8);

        float4 hp = make_float4(0.f, 0.f, 0.f, 0.f);
        if (t > 0) hp = *(const float4*)(h_prev + (size_t)gi * 256 + j);
        float hps[4] = {hp.x, hp.y, hp.z, hp.w};
        float hn[4];
#pragma unroll
        for (int u = 0; u < 4; u++) {
            float r = sigmoidf_(XW[3 * u] + BI[3 * u] + GH[3 * u] + BH[3 * u]);
            float z = sigmoidf_(XW[3 * u + 1] + BI[3 * u + 1] + GH[3 * u + 1] + BH[3 * u + 1]);
            float n = tanhf(XW[3 * u + 2] + BI[3 * u + 2] + r * (GH[3 * u + 2] + BH[3 * u + 2]));
            hn[u] = (1.f - z) * n + z * hps[u];
        }
        float4 hv = make_float4(hn[0], hn[1], hn[2], hn[3]);
        *(float4*)(h_out + (size_t)gi * 256 + j) = hv;
        if (len_s[row] == t + 1)
            *(float4*)(his_last + (size_t)orig * 256 + j) = hv;
    }
}

// ---------------- wide tf32 GEMM (intra xw): tile 64x192 ---------------------------
__global__ void __launch_bounds__(256, 2) gemm_tc_wide(
    int M, int K,
    const float* __restrict__ A, int lda,
    const float* __restrict__ W, int ldw,
    float* __restrict__ C, int ldc)
{
    __shared__ float smem[64 * 36 + 192 * 36];
    float* As = smem;
    float* Bs = smem + 64 * 36;
    float* Cs = smem;

    int i0 = blockIdx.x * 64, n0 = blockIdx.y * 192;
    int tid = threadIdx.x;
    int warp = tid >> 5, wy = warp >> 2, wx = warp & 3;

    wmma::fragment<wmma::accumulator, 16, 16, 8, float> acc[2][3];
#pragma unroll
    for (int a = 0; a < 2; a++)
#pragma unroll
        for (int b = 0; b < 3; b++) wmma::fill_fragment(acc[a][b], 0.f);

    float4 ra[2], rb[6];
    auto ldchunk = [&](int k0) {
#pragma unroll
        for (int it = 0; it < 2; it++) {
            int idx = tid + it * 256;
            int r = idx >> 3, k4 = (idx & 7) << 2;
            float4 v = make_float4(0.f, 0.f, 0.f, 0.f);
            if (i0 + r < M) v = *(const float4*)(A + (size_t)(i0 + r) * lda + k0 + k4);
            ra[it] = v;
        }
#pragma unroll
        for (int it = 0; it < 6; it++) {
            int idx = tid + it * 256;
            int c = idx >> 3, k4 = (idx & 7) << 2;
            rb[it] = *(const float4*)(W + (size_t)(n0 + c) * ldw + k0 + k4);
        }
    };
    auto stchunk = [&]() {
#pragma unroll
        for (int it = 0; it < 2; it++) {
            int idx = tid + it * 256;
            int r = idx >> 3, k4 = (idx & 7) << 2;
            *(float4*)(As + r * 36 + k4) = tf32_4(ra[it]);
        }
#pragma unroll
        for (int it = 0; it < 6; it++) {
            int idx = tid + it * 256;
            int c = idx >> 3, k4 = (idx & 7) << 2;
            *(float4*)(Bs + c * 36 + k4) = tf32_4(rb[it]);
        }
    };

    ldchunk(0); stchunk(); __syncthreads();
    for (int k0 = 0; k0 < K; k0 += 32) {
        bool more = (k0 + 32) < K;
        if (more) ldchunk(k0 + 32);
#pragma unroll
        for (int kk = 0; kk < 32; kk += 8) {
            wmma::fragment<wmma::matrix_a, 16, 16, 8, wmma::precision::tf32, wmma::row_major> af[2];
            wmma::fragment<wmma::matrix_b, 16, 16, 8, wmma::precision::tf32, wmma::col_major> bf[3];
#pragma unroll
            for (int fy = 0; fy < 2; fy++)
                wmma::load_matrix_sync(af[fy], As + (wy * 32 + fy * 16) * 36 + kk, 36);
#pragma unroll
            for (int fx = 0; fx < 3; fx++)
                wmma::load_matrix_sync(bf[fx], Bs + (wx * 48 + fx * 16) * 36 + kk, 36);
#pragma unroll
            for (int fy = 0; fy < 2; fy++)
#pragma unroll
                for (int fx = 0; fx < 3; fx++)
                    wmma::mma_sync(acc[fy][fx], af[fy], bf[fx], acc[fy][fx]);
        }
        __syncthreads();
        if (more) { stchunk(); __syncthreads(); }
    }

    for (int pass = 0; pass < 2; pass++) {
        __syncthreads();
        if (wy == pass) {
#pragma unroll
            for (int fy = 0; fy < 2; fy++)
#pragma unroll
                for (int fx = 0; fx < 3; fx++)
                    wmma::store_matrix_sync(Cs + (fy * 16) * 196 + wx * 48 + fx * 16,
                                            acc[fy][fx], 196, wmma::mem_row_major);
        }
        __syncthreads();
#pragma unroll
        for (int it = 0; it < 6; it++) {
            int idx = tid + it * 256;
            int row = idx / 48, c4 = (idx % 48) << 2;
            int gi = i0 + pass * 32 + row;
            if (gi >= M) continue;
            float4 v = *(float4*)(Cs + row * 196 + c4);
            *(float4*)(C + (size_t)gi * ldc + n0 + c4) = v;
        }
    }
}

// ---------------- tf32 GEMM (tile 128x64): C = A @ W^T + bias ----------------------
__global__ void __launch_bounds__(256, 2) gemm_tc(
    int M, int N, int K,
    const float* __restrict__ A, int lda,
    const float* __restrict__ W, int ldw,
    const float* __restrict__ bias,
    float* __restrict__ C, int ldc)
{
    __shared__ float smem[128 * 68];
    float* As = smem;
    float* Bs = smem + 128 * 40;

    int i0 = blockIdx.x * 128, n0 = blockIdx.y * 64;
    int tid = threadIdx.x;
    int warp = tid >> 5;
    int wy = warp >> 1, wx = warp & 1;

    wmma::fragment<wmma::accumulator, 16, 16, 8, float> acc[2][2];
#pragma unroll
    for (int a = 0; a < 2; a++)
#pragma unroll
        for (int b = 0; b < 2; b++) wmma::fill_fragment(acc[a][b], 0.f);

    float4 ra[4], rb[2];
    auto ldchunk = [&](int k0) {
#pragma unroll
        for (int it = 0; it < 4; it++) {
            int idx = tid + it * 256;
            int r = idx >> 3, k4 = (idx & 7) << 2;
            float4 v = make_float4(0.f, 0.f, 0.f, 0.f);
            int gi = i0 + r;
            if (gi < M) v = *(const float4*)(A + (size_t)gi * lda + k0 + k4);
            ra[it] = v;
        }
#pragma unroll
        for (int it = 0; it < 2; it++) {
            int idx = tid + it * 256;
            int n = idx >> 3, k4 = (idx & 7) << 2;
            rb[it] = *(const float4*)(W + (size_t)(n0 + n) * ldw + k0 + k4);
        }
    };
    auto stchunk = [&]() {
#pragma unroll
        for (int it = 0; it < 4; it++) {
            int idx = tid + it * 256;
            int r = idx >> 3, k4 = (idx & 7) << 2;
            *(float4*)(As + r * 40 + k4) = tf32_4(ra[it]);
        }
#pragma unroll
        for (int it = 0; it < 2; it++) {
            int idx = tid + it * 256;
            int n = idx >> 3, k4 = (idx & 7) << 2;
            *(float4*)(Bs + n * 40 + k4) = tf32_4(rb[it]);
        }
    };

    ldchunk(0); stchunk(); __syncthreads();
    for (int k0 = 0; k0 < K; k0 += 32) {
        bool more = (k0 + 32) < K;
        if (more) ldchunk(k0 + 32);
#pragma unroll
        for (int kk = 0; kk < 32; kk += 8) {
            wmma::fragment<wmma::matrix_a, 16, 16, 8, wmma::precision::tf32, wmma::row_major> af[2];
            wmma::fragment<wmma::matrix_b, 16, 16, 8, wmma::precision::tf32, wmma::col_major> bf[2];
#pragma unroll
            for (int fy = 0; fy < 2; fy++)
                wmma::load_matrix_sync(af[fy], As + (wy * 32 + fy * 16) * 40 + kk, 40);
#pragma unroll
            for (int fx = 0; fx < 2; fx++)
                wmma::load_matrix_sync(bf[fx], Bs + (wx * 32 + fx * 16) * 40 + kk, 40);
#pragma unroll
            for (int fy = 0; fy < 2; fy++)
#pragma unroll
                for (int fx = 0; fx < 2; fx++)
                    wmma::mma_sync(acc[fy][fx], af[fy], bf[fx], acc[fy][fx]);
        }
        __syncthreads();
        if (more) { stchunk(); __syncthreads(); }
    }

    float* Cs = smem;
#pragma unroll
    for (int fy = 0; fy < 2; fy++)
#pragma unroll
        for (int fx = 0; fx < 2; fx++)
            wmma::store_matrix_sync(Cs + (wy * 32 + fy * 16) * 68 + wx * 32 + fx * 16,
                                    acc[fy][fx], 68, wmma::mem_row_major);
    __syncthreads();
#pragma unroll
    for (int it = 0; it < 8; it++) {
        int idx = tid + it * 256;
        int r = idx >> 4, c4 = (idx & 15) << 2;
        int gi = i0 + r;
        if (gi >= M) continue;
        float4 v = *(float4*)(Cs + r * 68 + c4);
        if (bias) {
            v.x += bias[n0 + c4];     v.y += bias[n0 + c4 + 1];
            v.z += bias[n0 + c4 + 2]; v.w += bias[n0 + c4 + 3];
        }
        *(float4*)(C + (size_t)gi * ldc + n0 + c4) = v;
    }
}

// ---------------- fused intra GRU: coalesced transposed weights --------------------
__global__ void __launch_bounds__(768) intra_gru(
    const float* __restrict__ xw_intra,
    const float* __restrict__ w_hhT,
    const float* __restrict__ b_ih, const float* __restrict__ b_hh,
    float* __restrict__ intra_h)
{
    int b = blockIdx.x;
    int tid = threadIdx.x;
    __shared__ float h_sh[256];
    __shared__ float gh_sh[768];
    if (tid < 256) h_sh[tid] = 0.f;
    __syncthreads();
    for (int t = 0; t < Ss; t++) {
        float a0 = 0.f, a1 = 0.f, a2 = 0.f, a3 = 0.f;
#pragma unroll 16
        for (int k = 0; k < 256; k += 4) {
            a0 += w_hhT[(size_t)(k + 0) * 768 + tid] * h_sh[k + 0];
            a1 += w_hhT[(size_t)(k + 1) * 768 + tid] * h_sh[k + 1];
            a2 += w_hhT[(size_t)(k + 2) * 768 + tid] * h_sh[k + 2];
            a3 += w_hhT[(size_t)(k + 3) * 768 + tid] * h_sh[k + 3];
        }
        gh_sh[tid] = (a0 + a1) + (a2 + a3);
        __syncthreads();
        if (tid < 256) {
            const float* xwrow = xw_intra + ((size_t)b * Ss + t) * 768;
            float r = sigmoidf_(xwrow[3 * tid] + b_ih[tid] + gh_sh[tid] + b_hh[tid]);
            float z = sigmoidf_(xwrow[3 * tid + 1] + b_ih[256 + tid] + gh_sh[256 + tid] + b_hh[256 + tid]);
            float n = tanhf(xwrow[3 * tid + 2] + b_ih[512 + tid] + r * (gh_sh[512 + tid] + b_hh[512 + tid]));
            float hn = (1.f - z) * n + z * h_sh[tid];
            h_sh[tid] = hn;
            intra_h[((size_t)b * Ss + t) * 256 + tid] = hn;
        }
        __syncthreads();
    }
}

// ---------------- build_feat ----------------
__global__ void build_feat(const float* __restrict__ intra_x, const float* __restrict__ wr,
                           const float* __restrict__ vv, const float* __restrict__ vh,
                           const float* __restrict__ intra_h, float* __restrict__ feat) {
    int idx = blockIdx.x * blockDim.x + threadIdx.x;
    if (idx >= BS * 640) return;
    float e0 = expf(wr[0]), e1 = expf(wr[1]);
    float w0 = e0 / (e0 + e1), w1 = 1.f - w0;
    int i = idx / 640, c = idx % 640;
    float v;
    if (c < 256) v = w0 * vv[i * 256 + c] + w1 * vh[i * 256 + c];
    else if (c < 512) v = intra_h[i * 256 + (c - 256)];
    else if (c < 639) v = intra_x[i * 128 + (c - 512)];
    else v = 0.f;
    feat[idx] = v;
}

// ---------------- attention cores ----------------
__global__ void __launch_bounds__(256) inter_attn2(
    const float* __restrict__ qi, const float* __restrict__ kvi, float* __restrict__ oi)
{
    int warp = threadIdx.x >> 5, lane = threadIdx.x & 31;
    int item = blockIdx.x * 8 + warp;
    int row = item >> 1, head = item & 1;
    int off = head * 128 + lane * 4;

    float4 q = *(const float4*)(qi + (size_t)row * 256 + off);
    float p[6];
#pragma unroll
    for (int r = 0; r < 6; r++) {
        float4 k4 = *(const float4*)(kvi + (size_t)(row * 6 + r) * 512 + off);
        float d = q.x * k4.x + q.y * k4.y + q.z * k4.z + q.w * k4.w;
#pragma unroll
        for (int o = 16; o; o >>= 1) d += __shfl_xor_sync(0xffffffffu, d, o);
        p[r] = d * 0.08838834764831843f;
    }
    float mx = p[0];
#pragma unroll
    for (int r = 1; r < 6; r++) mx = fmaxf(mx, p[r]);
    float sum = 0.f;
#pragma unroll
    for (int r = 0; r < 6; r++) { p[r] = expf(p[r] - mx); sum += p[r]; }
    float inv = 1.f / sum;
    float4 acc = make_float4(0.f, 0.f, 0.f, 0.f);
#pragma unroll
    for (int r = 0; r < 6; r++) {
        float4 v4 = *(const float4*)(kvi + (size_t)(row * 6 + r) * 512 + 256 + off);
        float w = p[r] * inv;
        acc.x += w * v4.x; acc.y += w * v4.y; acc.z += w * v4.z; acc.w += w * v4.w;
    }
    *(float4*)(oi + (size_t)row * 256 + off) = acc;
}

__global__ void __launch_bounds__(256) intra_attn2(
    const float* __restrict__ qkh,
    const float* __restrict__ vhp, float* __restrict__ oh)
{
    extern __shared__ float sm[];
    float* Qs = sm + IA_QS;
    float* Ks = sm + IA_KS;
    float* Vs = sm + IA_VS;
    float* Ps = sm + IA_PS;

    int head = blockIdx.x, b = blockIdx.y;
    int tid = threadIdx.x;

    for (int idx = tid; idx < 64 * 32; idx += 256) {
        int row = idx >> 5, c4 = (idx & 31) << 2;
        size_t gq = (size_t)(b * 64 + row) * 512 + head * 128 + c4;
        size_t gv = (size_t)(b * 64 + row) * 256 + head * 128 + c4;
        *(float4*)(Qs + row * 132 + c4) = *(const float4*)(qkh + gq);
        *(float4*)(Ks + row * 132 + c4) = *(const float4*)(qkh + gq + 256);
        *(float4*)(Vs + row * 132 + c4) = *(const float4*)(vhp + gv);
    }
    __syncthreads();

    for (int idx = tid; idx < 64 * 64; idx += 256) {
        int tq = idx >> 6, tk = idx & 63;
        if (tk > tq) continue;
        const float4* qp = (const float4*)(Qs + tq * 132);
        const float4* kp = (const float4*)(Ks + tk * 132);
        float acc = 0.f;
#pragma unroll
        for (int k = 0; k < 32; k++) {
            float4 a = qp[k], c = kp[k];
            acc += a.x * c.x + a.y * c.y + a.z * c.z + a.w * c.w;
        }
        Ps[tq * 65 + tk] = acc * 0.08838834764831843f;
    }
    __syncthreads();

    if (tid < 64) {
        int tq = tid;
        float mx = -1e30f;
        for (int k = 0; k <= tq; k++) mx = fmaxf(mx, Ps[tq * 65 + k]);
        float sum = 0.f;
        for (int k = 0; k <= tq; k++) { float e = expf(Ps[tq * 65 + k] - mx); Ps[tq * 65 + k] = e; sum += e; }
        float inv = 1.f / sum;
        for (int k = 0; k <= tq; k++) Ps[tq * 65 + k] *= inv;
    }
    __syncthreads();

    for (int idx = tid; idx < 64 * 32; idx += 256) {
        int tq = idx >> 5, d4 = (idx & 31) << 2;
        float4 acc = make_float4(0.f, 0.f, 0.f, 0.f);
        for (int k = 0; k <= tq; k++) {
            float w = Ps[tq * 65 + k];
            float4 v = *(float4*)(Vs + k * 132 + d4);
            acc.x += w * v.x; acc.y += w * v.y; acc.z += w * v.z; acc.w += w * v.w;
        }
        *(float4*)(oh + (size_t)(b * 64 + tq) * 256 + head * 128 + d4) = acc;
    }
}

// ---------------- launch ----------------
extern "C" void kernel_launch(void* const* d_in, const int* in_sizes, int n_in,
                              void* d_out, int out_size) {
    const float* intra_x   = (const float*)d_in[0];
    const float* inter_his = (const float*)d_in[1];
    const float* inter_r   = (const float*)d_in[2];
    const int*   inter_len = (const int*)d_in[4];
    const float* w_ih = (const float*)d_in[5];
    const float* w_hh = (const float*)d_in[6];
    const float* b_ih = (const float*)d_in[7];
    const float* b_hh = (const float*)d_in[8];
    const float* iq_w = (const float*)d_in[9];
    const float* iq_b = (const float*)d_in[10];
    const float* ik_w = (const float*)d_in[11];
    const float* ik_b = (const float*)d_in[12];
    const float* iv_w = (const float*)d_in[13];
    const float* iv_b = (const float*)d_in[14];
    const float* io_w = (const float*)d_in[15];
    const float* io_b = (const float*)d_in[16];
    const float* aq_w = (const float*)d_in[17];
    const float* aq_b = (const float*)d_in[18];
    const float* ak_w = (const float*)d_in[19];
    const float* ak_b = (const float*)d_in[20];
    const float* av_w = (const float*)d_in[21];
    const float* av_b = (const float*)d_in[22];
    const float* ao_w = (const float*)d_in[23];
    const float* ao_b = (const float*)d_in[24];
    const float* wr   = (const float*)d_in[25];
    const float* ln_w = (const float*)d_in[26];
    const float* ln_b = (const float*)d_in[27];
    float* out = (float*)d_out;

    float *p_Whh_i, *p_WhhT, *p_Wih_i, *p_bias_i, *p_xw, *p_xw_intra, *p_hA, *p_hB, *p_his, *p_ih;
    float *p_Mrv, *p_mpv, *p_hp, *p_qi, *p_kvi, *p_oi, *p_vv, *p_qkh, *p_vhp;
    float *p_oh, *p_vh, *p_feat, *p_Wq, *p_Wkv, *p_bias_kv, *p_Waqk, *p_bias_aqk, *p_Wav, *p_Wln;
    int *p_perm, *p_cnt;
    cudaGetSymbolAddress((void**)&p_Whh_i, g_Whh_i);
    cudaGetSymbolAddress((void**)&p_WhhT, g_WhhT);
    cudaGetSymbolAddress((void**)&p_Wih_i, g_Wih_i);
    cudaGetSymbolAddress((void**)&p_bias_i, g_bias_i);
    cudaGetSymbolAddress((void**)&p_xw, g_xw_inter);
    cudaGetSymbolAddress((void**)&p_xw_intra, g_xw_intra);
    cudaGetSymbolAddress((void**)&p_hA, g_hA);
    cudaGetSymbolAddress((void**)&p_hB, g_hB);
    cudaGetSymbolAddress((void**)&p_his, g_his_last);
    cudaGetSymbolAddress((void**)&p_ih, g_intra_h);
    cudaGetSymbolAddress((void**)&p_Mrv, g_Mrv);
    cudaGetSymbolAddress((void**)&p_mpv, g_mpv);
    cudaGetSymbolAddress((void**)&p_hp, g_hp);
    cudaGetSymbolAddress((void**)&p_qi, g_qi);
    cudaGetSymbolAddress((void**)&p_kvi, g_kvi);
    cudaGetSymbolAddress((void**)&p_oi, g_oi);
    cudaGetSymbolAddress((void**)&p_vv, g_vv);
    cudaGetSymbolAddress((void**)&p_qkh, g_qkh);
    cudaGetSymbolAddress((void**)&p_vhp, g_vhp);
    cudaGetSymbolAddress((void**)&p_oh, g_oh);
    cudaGetSymbolAddress((void**)&p_vh, g_vh);
    cudaGetSymbolAddress((void**)&p_feat, g_feat);
    cudaGetSymbolAddress((void**)&p_Wq, g_Wq);
    cudaGetSymbolAddress((void**)&p_Wkv, g_Wkv);
    cudaGetSymbolAddress((void**)&p_bias_kv, g_bias_kv);
    cudaGetSymbolAddress((void**)&p_Waqk, g_Waqk);
    cudaGetSymbolAddress((void**)&p_bias_aqk, g_bias_aqk);
    cudaGetSymbolAddress((void**)&p_Wav, g_Wav);
    cudaGetSymbolAddress((void**)&p_Wln, g_Wln);
    cudaGetSymbolAddress((void**)&p_perm, g_perm);
    cudaGetSymbolAddress((void**)&p_cnt, g_cnt);

    static cudaStream_t s1 = nullptr;
    static cudaEvent_t ev_fork = nullptr, ev_pad = nullptr, ev_join = nullptr;
    static bool attr_set = false;
    if (!attr_set) {
        cudaFuncSetAttribute(gemm96_cp, cudaFuncAttributeMaxDynamicSharedMemorySize, SMEMF * 4);
        cudaFuncSetAttribute(gru_step96, cudaFuncAttributeMaxDynamicSharedMemorySize, GSMEMF * 4);
        cudaFuncSetAttribute(intra_attn2, cudaFuncAttributeMaxDynamicSharedMemorySize, IA_FLOATS * 4);
        cudaStreamCreateWithFlags(&s1, cudaStreamNonBlocking);
        cudaEventCreateWithFlags(&ev_fork, cudaEventDisableTiming);
        cudaEventCreateWithFlags(&ev_pad, cudaEventDisableTiming);
        cudaEventCreateWithFlags(&ev_join, cudaEventDisableTiming);
        attr_set = true;
    }

    // ---- prep (main stream)
    len_sort_all<<<1, 1024>>>(inter_len);
    prep_whh_i<<<(768 * 256 + 255) / 256, 256>>>(w_hh, p_Whh_i);
    prep_bias_i<<<3, 256>>>(b_ih, b_hh, p_bias_i);
    prep_wih_i<<<(768 * 128 + 255) / 256, 256>>>(w_ih, p_Wih_i);

    // ---- fork: entire intra side runs concurrently with the inter pipeline
    cudaEventRecord(ev_fork, 0);
    cudaStreamWaitEvent(s1, ev_fork, 0);
    prep_whhT<<<(256 * 768 + 255) / 256, 256, 0, s1>>>(w_hh, p_WhhT);
    gemm_tc_wide<<<dim3(16, 4), 256, 0, s1>>>(BS, 128, intra_x, 128, p_Wih_i, 128, p_xw_intra, 768);
    intra_gru<<<Bb, 768, 0, s1>>>(p_xw_intra, p_WhhT, b_ih, b_hh, p_ih);
    pad_all<<<(599040 + 255) / 256, 256, 0, s1>>>(iq_w, ik_w, iv_w, aq_w, ak_w, av_w, ln_w,
                                                  ik_b, iv_b, aq_b, ak_b);
    cudaEventRecord(ev_pad, s1);
    build_intra<<<(BS * 384 + BS * 257 + 255) / 256, 256, 0, s1>>>(intra_x);
    // inter-MHA q projection (depends on mpv = intra state, NOT the chain)
    gemm_tc<<<dim3(8, 4), 256, 0, s1>>>(BS, 256, 384, p_mpv, 384, p_Wq, 384, iq_b, p_qi, 256);
    // intra MHA, fully on s1
    gemm_tc<<<dim3(8, 8), 256, 0, s1>>>(BS, 512, 128, intra_x, 128, p_Waqk, 128, p_bias_aqk, p_qkh, 512);
    gemm_tc<<<dim3(8, 4), 256, 0, s1>>>(BS, 256, 288, p_hp, 288, p_Wav, 288, av_b, p_vhp, 256);
    intra_attn2<<<dim3(2, 16), 256, IA_FLOATS * 4, s1>>>(p_qkh, p_vhp, p_oh);
    gemm_tc<<<dim3(8, 4), 256, 0, s1>>>(BS, 256, 256, p_oh, 256, ao_w, 256, ao_b, p_vh, 256);
    cudaEventRecord(ev_join, s1);

    // ---- main stream: hoisted inter input projection + GRU chain
    gemm96_cp<<<NROWS_XW / 96, 256, SMEMF * 4>>>(inter_his, p_Wih_i, p_xw, inter_len);
    for (int t = 0; t < Ll; t++) {
        float* h_out  = (t & 1) ? p_hB : p_hA;
        float* h_prev = (t & 1) ? p_hA : p_hB;
        gru_step96<<<dim3(NSEQ / 96, 8), 128, GSMEMF * 4>>>(t, p_Whh_i, p_xw, p_bias_i,
                                                            inter_len, p_perm, p_cnt,
                                                            h_prev, h_out, p_his);
    }

    // ---- inter tail (needs his_last; kvi needs pad_all; attn needs qi from s1)
    build_mrv<<<(NSEQ * 384 + 255) / 256, 256>>>(inter_r);
    cudaStreamWaitEvent(0, ev_pad, 0);
    gemm_tc<<<dim3(48, 8), 256>>>(NSEQ, 512, 384, p_Mrv, 384, p_Wkv, 384, p_bias_kv, p_kvi, 512);
    cudaStreamWaitEvent(0, ev_join, 0);
    inter_attn2<<<256, 256>>>(p_qi, p_kvi, p_oi);
    gemm_tc<<<dim3(8, 4), 256>>>(BS, 256, 256, p_oi, 256, io_w, 256, io_b, p_vv, 256);

    // combine + final projection
    build_feat<<<(BS * 640 + 255) / 256, 256>>>(intra_x, wr, p_vv, p_vh, p_ih, p_feat);
    gemm_tc<<<dim3(8, 4), 256>>>(BS, 256, 640, p_feat, 640, p_Wln, 640, ln_b, out, 256);
}